// round 3
// baseline (speedup 1.0000x reference)
#include <cuda_runtime.h>
#include <math.h>

#define L_Q   1024
#define BSZ   2
#define DIM   1024
#define NHEAD 16
#define DHEAD 64
#define NLAY  4
#define MLEN  1024
#define KLEN  2048
#define NE    (L_Q*BSZ*DIM)   /* 2097152 floats per (L,B,D) slab */

// ---------------- scratch (device globals; no allocation allowed) ----------------
__device__ float g_cat[(size_t)KLEN*BSZ*DIM];        // 16 MB
__device__ float g_wheads[(size_t)KLEN*BSZ*3*DIM];   // 50 MB
__device__ float g_pos[(size_t)KLEN*DIM];            // 8 MB
__device__ float g_rhead[(size_t)KLEN*DIM];          // 8 MB
__device__ float g_attnvec[NE];
__device__ float g_tmp[NE];
__device__ float g_core[NE];
__device__ float g_core2[NE];
__device__ float g_ff[NE];

// ---------------- simple float4 copy ----------------
__global__ void copy_kernel(float* __restrict__ dst, const float* __restrict__ src, int n4) {
    int i = blockIdx.x * blockDim.x + threadIdx.x;
    if (i < n4) ((float4*)dst)[i] = ((const float4*)src)[i];
}

// ---------------- positional embedding ----------------
__global__ void pos_kernel(float* __restrict__ pos) {
    int idx = blockIdx.x * blockDim.x + threadIdx.x;
    if (idx >= KLEN * DIM) return;
    int j = idx >> 10;           // 0..2047
    int i = idx & 1023;          // 0..1023
    int t = i & 511;
    float x = (float)(2 * t) * (1.0f / 1024.0f);
    float invf = expf(-x * 9.210340371976184f);   // 10000^{-x}
    float arg = (float)(KLEN - 1 - j) * invf;
    pos[idx] = (i < 512) ? sinf(arg) : cosf(arg);
}

// ---------------- 128x128x8 SGEMM, 8x8 per thread ----------------
__global__ __launch_bounds__(256) void sgemm_kernel(
    const float* __restrict__ A, const float* __restrict__ B, float* __restrict__ C,
    int M, int N, int K, const float* __restrict__ bias, int relu)
{
    __shared__ __align__(16) float As[8 * 128];
    __shared__ __align__(16) float Bs[8 * 128];
    const int tid = threadIdx.x;
    const int tm = tid & 15;          // row micro-tile (tm*8)
    const int tn = tid >> 4;          // col micro-tile (tn*8)
    const int bx = blockIdx.x, by = blockIdx.y;

    const int ar = tid >> 1;          // 0..127
    const int ac = (tid & 1) << 2;    // 0 or 4
    const int br = tid >> 5;          // 0..7
    const int bc = (tid & 31) << 2;   // 0..124

    const float* Ap = A + (size_t)(by * 128 + ar) * K + ac;
    const float* Bp = B + (size_t)br * N + bx * 128 + bc;

    float acc[8][8];
#pragma unroll
    for (int i = 0; i < 8; i++)
#pragma unroll
        for (int j = 0; j < 8; j++) acc[i][j] = 0.f;

    for (int kt = 0; kt < K; kt += 8) {
        float4 avv = *(const float4*)(Ap + kt);
        float4 bvv = *(const float4*)(Bp + (size_t)kt * N);
        __syncthreads();
        As[(ac + 0) * 128 + ar] = avv.x;
        As[(ac + 1) * 128 + ar] = avv.y;
        As[(ac + 2) * 128 + ar] = avv.z;
        As[(ac + 3) * 128 + ar] = avv.w;
        *(float4*)&Bs[br * 128 + bc] = bvv;
        __syncthreads();
#pragma unroll
        for (int kk = 0; kk < 8; kk++) {
            float a[8], b[8];
            *(float4*)&a[0] = *(const float4*)&As[kk * 128 + tm * 8];
            *(float4*)&a[4] = *(const float4*)&As[kk * 128 + tm * 8 + 4];
            *(float4*)&b[0] = *(const float4*)&Bs[kk * 128 + tn * 8];
            *(float4*)&b[4] = *(const float4*)&Bs[kk * 128 + tn * 8 + 4];
#pragma unroll
            for (int i = 0; i < 8; i++)
#pragma unroll
                for (int j = 0; j < 8; j++) acc[i][j] += a[i] * b[j];
        }
    }
    const int r0 = by * 128 + tm * 8;
    const int c0 = bx * 128 + tn * 8;
#pragma unroll
    for (int i = 0; i < 8; i++) {
#pragma unroll
        for (int j = 0; j < 8; j++) {
            float v = acc[i][j];
            if (bias) v += bias[c0 + j];
            if (relu) v = fmaxf(v, 0.f);
            C[(size_t)(r0 + i) * N + c0 + j] = v;
        }
    }
}

// ---------------- fused rel-attention (flash-style, rel-shift folded in) ----------------
// grid: (16 q-tiles, 32 = bi*16+head), 256 threads, Tq=Tk=64
// sR padded to 128 rows so sV/sP stay 16B-aligned.
#define ATTN_SMEM_FLOATS (64*65*3 + 128*65 + 64*68*2)   /* 29504 */
#define ATTN_SMEM_BYTES  (ATTN_SMEM_FLOATS * 4)

__global__ __launch_bounds__(256) void attn_kernel(
    const float* __restrict__ wh, const float* __restrict__ rh,
    const float* __restrict__ rwb, const float* __restrict__ rrb,
    float* __restrict__ av)
{
    extern __shared__ float sm[];
    float* sQw = sm;                   // [64][65]
    float* sQr = sQw + 64 * 65;        // [64][65]
    float* sK  = sQr + 64 * 65;        // [64][65]
    float* sR  = sK  + 64 * 65;        // [128][65] (127 used)
    float* sV  = sR  + 128 * 65;       // [64][68]  (16B aligned)
    float* sP  = sV  + 64 * 68;        // [64][68]  (16B aligned)

    const int i0 = blockIdx.x << 6;
    const int bi = blockIdx.y >> 4;
    const int hn = blockIdx.y & 15;
    const int tid = threadIdx.x;
    const int ti = tid >> 4;           // 0..15 : rows ti*4..+3
    const int tj = tid & 15;           // 0..15 : cols tj*4..+3
    const int hbase = hn << 6;

    // load Q tiles with biases folded in
    for (int idx = tid; idx < 4096; idx += 256) {
        const int r = idx >> 6, kk = idx & 63;
        float qv = wh[((size_t)((MLEN + i0 + r) * BSZ + bi)) * 3072 + hbase + kk];
        sQw[r * 65 + kk] = qv + rwb[hbase + kk];
        sQr[r * 65 + kk] = qv + rrb[hbase + kk];
    }

    float mrow[4], lrow[4], acc[4][4];
#pragma unroll
    for (int x = 0; x < 4; x++) {
        mrow[x] = -3e38f; lrow[x] = 0.f;
#pragma unroll
        for (int y = 0; y < 4; y++) acc[x][y] = 0.f;
    }

    const int dbase = (tj - ti) * 4 + 60;   // sR row for (y-x)=-3
    const int nkt = 17 + (i0 >> 6);
    for (int kt = 0; kt < nkt; kt++) {
        const int j0 = kt << 6;
        __syncthreads();
        for (int idx = tid; idx < 4096; idx += 256) {
            const int r = idx >> 6, kk = idx & 63;
            const size_t base = ((size_t)((j0 + r) * BSZ + bi)) * 3072 + hbase + kk;
            sK[r * 65 + kk] = wh[base + 1024];
            sV[r * 68 + kk] = wh[base + 2048];
        }
        const int rbase = j0 + MLEN - 1 - i0 - 63;
        for (int idx = tid; idx < 127 * 64; idx += 256) {
            const int r = idx >> 6, kk = idx & 63;
            int rg = rbase + r;
            rg = rg < 0 ? 0 : (rg > KLEN - 1 ? KLEN - 1 : rg);
            sR[r * 65 + kk] = rh[(size_t)rg * DIM + hbase + kk];
        }
        __syncthreads();

        float s[4][4];
#pragma unroll
        for (int x = 0; x < 4; x++)
#pragma unroll
            for (int y = 0; y < 4; y++) s[x][y] = 0.f;

        for (int kk = 0; kk < 64; kk++) {
            float kv[4], rv7[7], qw[4], qr[4];
#pragma unroll
            for (int y = 0; y < 4; y++) kv[y] = sK[(tj * 4 + y) * 65 + kk];
#pragma unroll
            for (int d = 0; d < 7; d++) rv7[d] = sR[(dbase + d) * 65 + kk];
#pragma unroll
            for (int x = 0; x < 4; x++) { qw[x] = sQw[(ti * 4 + x) * 65 + kk]; qr[x] = sQr[(ti * 4 + x) * 65 + kk]; }
#pragma unroll
            for (int x = 0; x < 4; x++)
#pragma unroll
                for (int y = 0; y < 4; y++)
                    s[x][y] += qw[x] * kv[y] + qr[x] * rv7[y - x + 3];
        }

        // mask + online softmax (rows split over 16 lanes tj)
#pragma unroll
        for (int x = 0; x < 4; x++) {
            const int qi = i0 + ti * 4 + x;
            float tmax = -3e38f;
            float p[4];
#pragma unroll
            for (int y = 0; y < 4; y++) {
                const int kj = j0 + tj * 4 + y;
                float v = s[x][y] * 0.125f;
                if (kj > MLEN + qi) v = -3e38f;
                s[x][y] = v;
                tmax = fmaxf(tmax, v);
            }
#pragma unroll
            for (int off = 1; off < 16; off <<= 1)
                tmax = fmaxf(tmax, __shfl_xor_sync(0xffffffffu, tmax, off));
            const float mnew = fmaxf(mrow[x], tmax);
            const float alpha = expf(mrow[x] - mnew);
            float rsum = 0.f;
#pragma unroll
            for (int y = 0; y < 4; y++) { p[y] = expf(s[x][y] - mnew); rsum += p[y]; }
#pragma unroll
            for (int off = 1; off < 16; off <<= 1)
                rsum += __shfl_xor_sync(0xffffffffu, rsum, off);
            lrow[x] = lrow[x] * alpha + rsum;
            mrow[x] = mnew;
#pragma unroll
            for (int y = 0; y < 4; y++) { acc[x][y] *= alpha; sP[(ti * 4 + x) * 68 + tj * 4 + y] = p[y]; }
        }
        __syncthreads();

        // P @ V
#pragma unroll 2
        for (int jl = 0; jl < 64; jl++) {
            float4 vv = *(const float4*)&sV[jl * 68 + tj * 4];
#pragma unroll
            for (int x = 0; x < 4; x++) {
                const float pv = sP[(ti * 4 + x) * 68 + jl];
                acc[x][0] += pv * vv.x; acc[x][1] += pv * vv.y;
                acc[x][2] += pv * vv.z; acc[x][3] += pv * vv.w;
            }
        }
    }

#pragma unroll
    for (int x = 0; x < 4; x++) {
        const float inv = 1.f / lrow[x];
        float4 o;
        o.x = acc[x][0] * inv; o.y = acc[x][1] * inv;
        o.z = acc[x][2] * inv; o.w = acc[x][3] * inv;
        const int qi = i0 + ti * 4 + x;
        *(float4*)&av[((size_t)(qi * BSZ + bi)) * DIM + hbase + tj * 4] = o;
    }
}

// ---------------- residual + layernorm (row per block) ----------------
__global__ __launch_bounds__(256) void ln_kernel(
    const float* __restrict__ x, const float* __restrict__ res,
    const float* __restrict__ g, const float* __restrict__ b,
    float* __restrict__ out1, float* __restrict__ out2)
{
    const int row = blockIdx.x;
    const int tid = threadIdx.x;
    float4 xv = *(const float4*)(x + (size_t)row * DIM + tid * 4);
    float4 rv = *(const float4*)(res + (size_t)row * DIM + tid * 4);
    float v0 = xv.x + rv.x, v1 = xv.y + rv.y, v2 = xv.z + rv.z, v3 = xv.w + rv.w;
    float s = v0 + v1 + v2 + v3;
    float q = v0 * v0 + v1 * v1 + v2 * v2 + v3 * v3;
#pragma unroll
    for (int off = 16; off > 0; off >>= 1) {
        s += __shfl_xor_sync(0xffffffffu, s, off);
        q += __shfl_xor_sync(0xffffffffu, q, off);
    }
    __shared__ float sb[8], qb[8];
    const int w = tid >> 5, lane = tid & 31;
    if (lane == 0) { sb[w] = s; qb[w] = q; }
    __syncthreads();
    if (w == 0) {
        float s2 = (lane < 8) ? sb[lane] : 0.f;
        float q2 = (lane < 8) ? qb[lane] : 0.f;
#pragma unroll
        for (int off = 4; off > 0; off >>= 1) {
            s2 += __shfl_xor_sync(0xffffffffu, s2, off);
            q2 += __shfl_xor_sync(0xffffffffu, q2, off);
        }
        if (lane == 0) { sb[0] = s2; qb[0] = q2; }
    }
    __syncthreads();
    const float mean = sb[0] * (1.0f / DIM);
    const float var  = qb[0] * (1.0f / DIM) - mean * mean;
    const float rstd = rsqrtf(var + 1e-5f);
    float4 gv = *(const float4*)(g + tid * 4);
    float4 bv = *(const float4*)(b + tid * 4);
    float4 o;
    o.x = (v0 - mean) * rstd * gv.x + bv.x;
    o.y = (v1 - mean) * rstd * gv.y + bv.y;
    o.z = (v2 - mean) * rstd * gv.z + bv.z;
    o.w = (v3 - mean) * rstd * gv.w + bv.w;
    *(float4*)(out1 + (size_t)row * DIM + tid * 4) = o;
    if (out2) *(float4*)(out2 + (size_t)row * DIM + tid * 4) = o;
}

// ---------------- host orchestration ----------------
extern "C" void kernel_launch(void* const* d_in, const int* in_sizes, int n_in,
                              void* d_out, int out_size) {
    const float* mems = (const float*)d_in[0];
    const float* raw  = (const float*)d_in[1];
    /* d_in[2] = attention_mask: analytic, ignored */
    const float* rwb  = (const float*)d_in[3];
    const float* rrb  = (const float*)d_in[4];
    const float* qkvw = (const float*)d_in[5];
    const float* rw   = (const float*)d_in[6];
    const float* ow   = (const float*)d_in[7];
    const float* ln1g = (const float*)d_in[8];
    const float* ln1b = (const float*)d_in[9];
    const float* fw1  = (const float*)d_in[10];
    const float* fb1  = (const float*)d_in[11];
    const float* fw2  = (const float*)d_in[12];
    const float* fb2  = (const float*)d_in[13];
    const float* ln2g = (const float*)d_in[14];
    const float* ln2b = (const float*)d_in[15];
    float* out = (float*)d_out;

    const bool full_out = out_size >= (NLAY + 2) * NE;   // core + new_mems(5 slabs)
    float* out_mems = full_out ? out + NE : nullptr;

    float *cat, *wh, *pos, *rh, *av, *tmp, *core, *core2, *ff;
    cudaGetSymbolAddress((void**)&cat,  g_cat);
    cudaGetSymbolAddress((void**)&wh,   g_wheads);
    cudaGetSymbolAddress((void**)&pos,  g_pos);
    cudaGetSymbolAddress((void**)&rh,   g_rhead);
    cudaGetSymbolAddress((void**)&av,   g_attnvec);
    cudaGetSymbolAddress((void**)&tmp,  g_tmp);
    cudaGetSymbolAddress((void**)&core, g_core);
    cudaGetSymbolAddress((void**)&core2,g_core2);
    cudaGetSymbolAddress((void**)&ff,   g_ff);

    cudaFuncSetAttribute((const void*)attn_kernel,
                         cudaFuncAttributeMaxDynamicSharedMemorySize, ATTN_SMEM_BYTES);

    const int C4 = NE / 4;               // float4 count per slab
    const int CB = (C4 + 255) / 256;

    copy_kernel<<<CB, 256>>>(core, raw, C4);
    if (out_mems) copy_kernel<<<CB, 256>>>(out_mems, raw, C4);
    pos_kernel<<<(KLEN * DIM + 255) / 256, 256>>>(pos);

    for (int i = 0; i < NLAY; i++) {
        copy_kernel<<<CB, 256>>>(cat, mems + (size_t)i * NE, C4);
        copy_kernel<<<CB, 256>>>(cat + NE, core, C4);

        sgemm_kernel<<<dim3(3072 / 128, 4096 / 128), 256>>>(
            cat, qkvw + (size_t)i * DIM * 3 * DIM, wh, 4096, 3072, 1024, nullptr, 0);
        sgemm_kernel<<<dim3(1024 / 128, 2048 / 128), 256>>>(
            pos, rw + (size_t)i * DIM * DIM, rh, 2048, 1024, 1024, nullptr, 0);

        attn_kernel<<<dim3(16, 32), 256, ATTN_SMEM_BYTES>>>(wh, rh, rwb, rrb, av);

        sgemm_kernel<<<dim3(8, 16), 256>>>(
            av, ow + (size_t)i * DIM * DIM, tmp, 2048, 1024, 1024, nullptr, 0);
        ln_kernel<<<2048, 256>>>(tmp, core, ln1g + i * DIM, ln1b + i * DIM, core2, nullptr);

        sgemm_kernel<<<dim3(8, 16), 256>>>(
            core2, fw1 + (size_t)i * DIM * DIM, ff, 2048, 1024, 1024, fb1 + i * DIM, 1);
        sgemm_kernel<<<dim3(8, 16), 256>>>(
            ff, fw2 + (size_t)i * DIM * DIM, tmp, 2048, 1024, 1024, fb2 + i * DIM, 0);
        ln_kernel<<<2048, 256>>>(tmp, core2, ln2g + i * DIM, ln2b + i * DIM, core,
                                 out_mems ? out_mems + (size_t)(i + 1) * NE : nullptr);
    }
    copy_kernel<<<CB, 256>>>(out, core, C4);
}

// round 5
// speedup vs baseline: 2.2085x; 2.2085x over previous
#include <cuda_runtime.h>
#include <math.h>
#include <stdint.h>

#define L_Q   1024
#define BSZ   2
#define DIM   1024
#define NHEAD 16
#define DHEAD 64
#define NLAY  4
#define MLEN  1024
#define KLEN  2048
#define NE    (L_Q*BSZ*DIM)   /* 2097152 floats per (L,B,D) slab */

// ---------------- scratch (device globals; no allocation allowed) ----------------
__device__ float g_cat[(size_t)KLEN*BSZ*DIM];        // 16 MB
__device__ float g_wheads[(size_t)KLEN*BSZ*3*DIM];   // 50 MB
__device__ float g_pos[(size_t)KLEN*DIM];            // 8 MB
__device__ float g_rhead[(size_t)KLEN*DIM];          // 8 MB
__device__ float g_attnvec[NE];
__device__ float g_tmp[NE];
__device__ float g_core[NE];
__device__ float g_core2[NE];
__device__ float g_ff[NE];

// ---------------- simple float4 copy ----------------
__global__ void copy_kernel(float* __restrict__ dst, const float* __restrict__ src, int n4) {
    int i = blockIdx.x * blockDim.x + threadIdx.x;
    if (i < n4) ((float4*)dst)[i] = ((const float4*)src)[i];
}

// ---------------- positional embedding ----------------
__global__ void pos_kernel(float* __restrict__ pos) {
    int idx = blockIdx.x * blockDim.x + threadIdx.x;
    if (idx >= KLEN * DIM) return;
    int j = idx >> 10;           // 0..2047
    int i = idx & 1023;          // 0..1023
    int t = i & 511;
    float x = (float)(2 * t) * (1.0f / 1024.0f);
    float invf = expf(-x * 9.210340371976184f);   // 10000^{-x}
    float arg = (float)(KLEN - 1 - j) * invf;
    pos[idx] = (i < 512) ? sinf(arg) : cosf(arg);
}

// ---------------- tf32 helpers ----------------
__device__ __forceinline__ uint32_t f2tf32(float f) {
    uint32_t u;
    asm("cvt.rna.tf32.f32 %0, %1;" : "=r"(u) : "f"(f));
    return u;
}
__device__ __forceinline__ void mma_tf32(float* c, const uint32_t* a, const uint32_t* b) {
    asm volatile(
        "mma.sync.aligned.m16n8k8.row.col.f32.tf32.tf32.f32 "
        "{%0,%1,%2,%3}, {%4,%5,%6,%7}, {%8,%9}, {%0,%1,%2,%3};"
        : "+f"(c[0]), "+f"(c[1]), "+f"(c[2]), "+f"(c[3])
        : "r"(a[0]), "r"(a[1]), "r"(a[2]), "r"(a[3]), "r"(b[0]), "r"(b[1]));
}

// ---------------- tf32 tensor-core GEMM: 128x128 block, K-tile 32 ----------------
// A row-major [M,K], B row-major [K,N], C row-major [M,N]. M%128==0, N%128==0, K%32==0.
// 8 warps: warp (wr,wc) with wr=w&1 (2 x 64 rows), wc=w>>1 (4 x 32 cols).
// SMEM fragment-permuted layout:
//   As[((ks*8+mb)*32 + lane)*4 + q]   : A 16x8 frag (mb of 8 m-blocks, ks of 4 k-steps)
//   Bs[((ks*16+nb)*32 + lane)*2 + q]  : B 8x8  frag (nb of 16 n-blocks)
__global__ __launch_bounds__(256) void mma_gemm(
    const float* __restrict__ A, const float* __restrict__ B, float* __restrict__ C,
    int M, int N, int K, const float* __restrict__ bias, int relu)
{
    __shared__ __align__(16) uint32_t As[4096];
    __shared__ __align__(16) uint32_t Bs[4096];

    const int tid = threadIdx.x;
    const int lane = tid & 31;
    const int w = tid >> 5;
    const int wr = w & 1;            // 0..1
    const int wc = w >> 1;           // 0..3
    const int bx = blockIdx.x, by = blockIdx.y;

    // staging coordinates
    const int sar = tid >> 1;                 // A row 0..127
    const int sac = (tid & 1) << 4;           // A col base 0 or 16
    const int sbk = tid >> 3;                 // B k-row 0..31
    const int sbn = (tid & 7) << 4;           // B col base 0..112

    const float* Ag = A + (size_t)(by * 128 + sar) * K + sac;
    const float* Bg = B + (size_t)sbk * N + bx * 128 + sbn;

    float acc[4][4][4];
#pragma unroll
    for (int mi = 0; mi < 4; mi++)
#pragma unroll
        for (int ni = 0; ni < 4; ni++)
#pragma unroll
            for (int q = 0; q < 4; q++) acc[mi][ni][q] = 0.f;

    float4 pa[4], pb[4];
    // preload tile 0
#pragma unroll
    for (int t = 0; t < 4; t++) {
        pa[t] = *(const float4*)(Ag + t * 4);
        pb[t] = *(const float4*)(Bg + (size_t)0 + t * 4);
    }

    for (int kt = 0; kt < K; kt += 32) {
        __syncthreads();
        // ---- stage regs -> smem (tf32 convert, permuted) ----
        {
            // A: element (sar, c) with c = sac + t*4 + i
            const int mb = sar >> 4;
            const int lbase = (sar & 7) << 2;
            const int rq = (sar >> 3) & 1;
#pragma unroll
            for (int t = 0; t < 4; t++) {
                const int c = sac + t * 4;
                const int ks = c >> 3;
                const int q = rq + 2 * ((c >> 2) & 1);
                uint32_t* dst = &As[(((ks * 8 + mb) * 32 + lbase) << 2) + q];
                const float* f = (const float*)&pa[t];
                dst[0]  = f2tf32(f[0]);
                dst[4]  = f2tf32(f[1]);
                dst[8]  = f2tf32(f[2]);
                dst[12] = f2tf32(f[3]);
            }
            // B: element (sbk, n) with n = sbn + t*4 + i
            const int ks = sbk >> 3;
            const int kq = (sbk >> 2) & 1;
            const int kt2 = (sbk & 3) << 1;
#pragma unroll
            for (int t = 0; t < 4; t++) {
                const int n = sbn + t * 4;
                const int nb = n >> 3;
                uint32_t* dst = &Bs[(((ks * 16 + nb) * 32 + ((n & 7) << 2)) << 1) + kt2 + kq];
                const float* f = (const float*)&pb[t];
                dst[0]  = f2tf32(f[0]);
                dst[8]  = f2tf32(f[1]);
                dst[16] = f2tf32(f[2]);
                dst[24] = f2tf32(f[3]);
            }
        }
        __syncthreads();

        // ---- prefetch next tile ----
        if (kt + 32 < K) {
#pragma unroll
            for (int t = 0; t < 4; t++) {
                pa[t] = *(const float4*)(Ag + (kt + 32) + t * 4);
                pb[t] = *(const float4*)(Bg + (size_t)(kt + 32) * N + t * 4);
            }
        }

        // ---- compute 4 k-steps ----
#pragma unroll
        for (int ks = 0; ks < 4; ks++) {
            uint32_t afr[4][4], bfr[4][2];
#pragma unroll
            for (int mi = 0; mi < 4; mi++) {
                const uint4 v = *(const uint4*)&As[(((ks * 8 + wr * 4 + mi) * 32 + lane) << 2)];
                afr[mi][0] = v.x; afr[mi][1] = v.y; afr[mi][2] = v.z; afr[mi][3] = v.w;
            }
#pragma unroll
            for (int ni = 0; ni < 4; ni++) {
                const uint2 v = *(const uint2*)&Bs[(((ks * 16 + wc * 4 + ni) * 32 + lane) << 1)];
                bfr[ni][0] = v.x; bfr[ni][1] = v.y;
            }
#pragma unroll
            for (int mi = 0; mi < 4; mi++)
#pragma unroll
                for (int ni = 0; ni < 4; ni++)
                    mma_tf32(acc[mi][ni], afr[mi], bfr[ni]);
        }
    }

    // ---- epilogue ----
    const int g = lane >> 2;
    const int t = lane & 3;
#pragma unroll
    for (int mi = 0; mi < 4; mi++) {
        const int r0 = by * 128 + wr * 64 + mi * 16 + g;
#pragma unroll
        for (int ni = 0; ni < 4; ni++) {
            const int c0 = bx * 128 + wc * 32 + ni * 8 + t * 2;
            float b0 = 0.f, b1 = 0.f;
            if (bias) { b0 = bias[c0]; b1 = bias[c0 + 1]; }
            float2 o0, o1;
            o0.x = acc[mi][ni][0] + b0; o0.y = acc[mi][ni][1] + b1;
            o1.x = acc[mi][ni][2] + b0; o1.y = acc[mi][ni][3] + b1;
            if (relu) {
                o0.x = fmaxf(o0.x, 0.f); o0.y = fmaxf(o0.y, 0.f);
                o1.x = fmaxf(o1.x, 0.f); o1.y = fmaxf(o1.y, 0.f);
            }
            *(float2*)&C[(size_t)r0 * N + c0] = o0;
            *(float2*)&C[(size_t)(r0 + 8) * N + c0] = o1;
        }
    }
}

// ---------------- fused rel-attention (flash-style, rel-shift folded in) ----------------
#define ATTN_SMEM_FLOATS (64*65*3 + 128*65 + 64*68*2)   /* 29504 */
#define ATTN_SMEM_BYTES  (ATTN_SMEM_FLOATS * 4)

__global__ __launch_bounds__(256) void attn_kernel(
    const float* __restrict__ wh, const float* __restrict__ rh,
    const float* __restrict__ rwb, const float* __restrict__ rrb,
    float* __restrict__ av)
{
    extern __shared__ float sm[];
    float* sQw = sm;                   // [64][65]
    float* sQr = sQw + 64 * 65;        // [64][65]
    float* sK  = sQr + 64 * 65;        // [64][65]
    float* sR  = sK  + 64 * 65;        // [128][65] (127 used)
    float* sV  = sR  + 128 * 65;       // [64][68]  (16B aligned)
    float* sP  = sV  + 64 * 68;        // [64][68]  (16B aligned)

    const int i0 = blockIdx.x << 6;
    const int bi = blockIdx.y >> 4;
    const int hn = blockIdx.y & 15;
    const int tid = threadIdx.x;
    const int ti = tid >> 4;           // 0..15 : rows ti*4..+3
    const int tj = tid & 15;           // 0..15 : cols tj*4..+3
    const int hbase = hn << 6;

    for (int idx = tid; idx < 4096; idx += 256) {
        const int r = idx >> 6, kk = idx & 63;
        float qv = wh[((size_t)((MLEN + i0 + r) * BSZ + bi)) * 3072 + hbase + kk];
        sQw[r * 65 + kk] = qv + rwb[hbase + kk];
        sQr[r * 65 + kk] = qv + rrb[hbase + kk];
    }

    float mrow[4], lrow[4], acc[4][4];
#pragma unroll
    for (int x = 0; x < 4; x++) {
        mrow[x] = -3e38f; lrow[x] = 0.f;
#pragma unroll
        for (int y = 0; y < 4; y++) acc[x][y] = 0.f;
    }

    const int dbase = (tj - ti) * 4 + 60;   // sR row for (y-x)=-3
    const int nkt = 17 + (i0 >> 6);
    for (int kt = 0; kt < nkt; kt++) {
        const int j0 = kt << 6;
        __syncthreads();
        for (int idx = tid; idx < 4096; idx += 256) {
            const int r = idx >> 6, kk = idx & 63;
            const size_t base = ((size_t)((j0 + r) * BSZ + bi)) * 3072 + hbase + kk;
            sK[r * 65 + kk] = wh[base + 1024];
            sV[r * 68 + kk] = wh[base + 2048];
        }
        const int rbase = j0 + MLEN - 1 - i0 - 63;
        for (int idx = tid; idx < 127 * 64; idx += 256) {
            const int r = idx >> 6, kk = idx & 63;
            int rg = rbase + r;
            rg = rg < 0 ? 0 : (rg > KLEN - 1 ? KLEN - 1 : rg);
            sR[r * 65 + kk] = rh[(size_t)rg * DIM + hbase + kk];
        }
        __syncthreads();

        float s[4][4];
#pragma unroll
        for (int x = 0; x < 4; x++)
#pragma unroll
            for (int y = 0; y < 4; y++) s[x][y] = 0.f;

        for (int kk = 0; kk < 64; kk++) {
            float kv[4], rv7[7], qw[4], qr[4];
#pragma unroll
            for (int y = 0; y < 4; y++) kv[y] = sK[(tj * 4 + y) * 65 + kk];
#pragma unroll
            for (int d = 0; d < 7; d++) rv7[d] = sR[(dbase + d) * 65 + kk];
#pragma unroll
            for (int x = 0; x < 4; x++) { qw[x] = sQw[(ti * 4 + x) * 65 + kk]; qr[x] = sQr[(ti * 4 + x) * 65 + kk]; }
#pragma unroll
            for (int x = 0; x < 4; x++)
#pragma unroll
                for (int y = 0; y < 4; y++)
                    s[x][y] += qw[x] * kv[y] + qr[x] * rv7[y - x + 3];
        }

#pragma unroll
        for (int x = 0; x < 4; x++) {
            const int qi = i0 + ti * 4 + x;
            float tmax = -3e38f;
            float p[4];
#pragma unroll
            for (int y = 0; y < 4; y++) {
                const int kj = j0 + tj * 4 + y;
                float v = s[x][y] * 0.125f;
                if (kj > MLEN + qi) v = -3e38f;
                s[x][y] = v;
                tmax = fmaxf(tmax, v);
            }
#pragma unroll
            for (int off = 1; off < 16; off <<= 1)
                tmax = fmaxf(tmax, __shfl_xor_sync(0xffffffffu, tmax, off));
            const float mnew = fmaxf(mrow[x], tmax);
            const float alpha = expf(mrow[x] - mnew);
            float rsum = 0.f;
#pragma unroll
            for (int y = 0; y < 4; y++) { p[y] = expf(s[x][y] - mnew); rsum += p[y]; }
#pragma unroll
            for (int off = 1; off < 16; off <<= 1)
                rsum += __shfl_xor_sync(0xffffffffu, rsum, off);
            lrow[x] = lrow[x] * alpha + rsum;
            mrow[x] = mnew;
#pragma unroll
            for (int y = 0; y < 4; y++) { acc[x][y] *= alpha; sP[(ti * 4 + x) * 68 + tj * 4 + y] = p[y]; }
        }
        __syncthreads();

#pragma unroll 2
        for (int jl = 0; jl < 64; jl++) {
            float4 vv = *(const float4*)&sV[jl * 68 + tj * 4];
#pragma unroll
            for (int x = 0; x < 4; x++) {
                const float pv = sP[(ti * 4 + x) * 68 + jl];
                acc[x][0] += pv * vv.x; acc[x][1] += pv * vv.y;
                acc[x][2] += pv * vv.z; acc[x][3] += pv * vv.w;
            }
        }
    }

#pragma unroll
    for (int x = 0; x < 4; x++) {
        const float inv = 1.f / lrow[x];
        float4 o;
        o.x = acc[x][0] * inv; o.y = acc[x][1] * inv;
        o.z = acc[x][2] * inv; o.w = acc[x][3] * inv;
        const int qi = i0 + ti * 4 + x;
        *(float4*)&av[((size_t)(qi * BSZ + bi)) * DIM + hbase + tj * 4] = o;
    }
}

// ---------------- residual + layernorm (row per block) ----------------
__global__ __launch_bounds__(256) void ln_kernel(
    const float* __restrict__ x, const float* __restrict__ res,
    const float* __restrict__ g, const float* __restrict__ b,
    float* __restrict__ out1, float* __restrict__ out2)
{
    const int row = blockIdx.x;
    const int tid = threadIdx.x;
    float4 xv = *(const float4*)(x + (size_t)row * DIM + tid * 4);
    float4 rv = *(const float4*)(res + (size_t)row * DIM + tid * 4);
    float v0 = xv.x + rv.x, v1 = xv.y + rv.y, v2 = xv.z + rv.z, v3 = xv.w + rv.w;
    float s = v0 + v1 + v2 + v3;
    float q = v0 * v0 + v1 * v1 + v2 * v2 + v3 * v3;
#pragma unroll
    for (int off = 16; off > 0; off >>= 1) {
        s += __shfl_xor_sync(0xffffffffu, s, off);
        q += __shfl_xor_sync(0xffffffffu, q, off);
    }
    __shared__ float sb[8], qb[8];
    const int w = tid >> 5, lane = tid & 31;
    if (lane == 0) { sb[w] = s; qb[w] = q; }
    __syncthreads();
    if (w == 0) {
        float s2 = (lane < 8) ? sb[lane] : 0.f;
        float q2 = (lane < 8) ? qb[lane] : 0.f;
#pragma unroll
        for (int off = 4; off > 0; off >>= 1) {
            s2 += __shfl_xor_sync(0xffffffffu, s2, off);
            q2 += __shfl_xor_sync(0xffffffffu, q2, off);
        }
        if (lane == 0) { sb[0] = s2; qb[0] = q2; }
    }
    __syncthreads();
    const float mean = sb[0] * (1.0f / DIM);
    const float var  = qb[0] * (1.0f / DIM) - mean * mean;
    const float rstd = rsqrtf(var + 1e-5f);
    float4 gv = *(const float4*)(g + tid * 4);
    float4 bv = *(const float4*)(b + tid * 4);
    float4 o;
    o.x = (v0 - mean) * rstd * gv.x + bv.x;
    o.y = (v1 - mean) * rstd * gv.y + bv.y;
    o.z = (v2 - mean) * rstd * gv.z + bv.z;
    o.w = (v3 - mean) * rstd * gv.w + bv.w;
    *(float4*)(out1 + (size_t)row * DIM + tid * 4) = o;
    if (out2) *(float4*)(out2 + (size_t)row * DIM + tid * 4) = o;
}

// ---------------- host orchestration ----------------
extern "C" void kernel_launch(void* const* d_in, const int* in_sizes, int n_in,
                              void* d_out, int out_size) {
    const float* mems = (const float*)d_in[0];
    const float* raw  = (const float*)d_in[1];
    /* d_in[2] = attention_mask: analytic, ignored */
    const float* rwb  = (const float*)d_in[3];
    const float* rrb  = (const float*)d_in[4];
    const float* qkvw = (const float*)d_in[5];
    const float* rw   = (const float*)d_in[6];
    const float* ow   = (const float*)d_in[7];
    const float* ln1g = (const float*)d_in[8];
    const float* ln1b = (const float*)d_in[9];
    const float* fw1  = (const float*)d_in[10];
    const float* fb1  = (const float*)d_in[11];
    const float* fw2  = (const float*)d_in[12];
    const float* fb2  = (const float*)d_in[13];
    const float* ln2g = (const float*)d_in[14];
    const float* ln2b = (const float*)d_in[15];
    float* out = (float*)d_out;

    const bool full_out = out_size >= (NLAY + 2) * NE;   // core + new_mems(5 slabs)
    float* out_mems = full_out ? out + NE : nullptr;

    float *cat, *wh, *pos, *rh, *av, *tmp, *core, *core2, *ff;
    cudaGetSymbolAddress((void**)&cat,  g_cat);
    cudaGetSymbolAddress((void**)&wh,   g_wheads);
    cudaGetSymbolAddress((void**)&pos,  g_pos);
    cudaGetSymbolAddress((void**)&rh,   g_rhead);
    cudaGetSymbolAddress((void**)&av,   g_attnvec);
    cudaGetSymbolAddress((void**)&tmp,  g_tmp);
    cudaGetSymbolAddress((void**)&core, g_core);
    cudaGetSymbolAddress((void**)&core2,g_core2);
    cudaGetSymbolAddress((void**)&ff,   g_ff);

    cudaFuncSetAttribute((const void*)attn_kernel,
                         cudaFuncAttributeMaxDynamicSharedMemorySize, ATTN_SMEM_BYTES);

    const int C4 = NE / 4;               // float4 count per slab
    const int CB = (C4 + 255) / 256;

    copy_kernel<<<CB, 256>>>(core, raw, C4);
    if (out_mems) copy_kernel<<<CB, 256>>>(out_mems, raw, C4);
    pos_kernel<<<(KLEN * DIM + 255) / 256, 256>>>(pos);

    for (int i = 0; i < NLAY; i++) {
        copy_kernel<<<CB, 256>>>(cat, mems + (size_t)i * NE, C4);
        copy_kernel<<<CB, 256>>>(cat + NE, core, C4);

        mma_gemm<<<dim3(3072 / 128, 4096 / 128), 256>>>(
            cat, qkvw + (size_t)i * DIM * 3 * DIM, wh, 4096, 3072, 1024, nullptr, 0);
        mma_gemm<<<dim3(1024 / 128, 2048 / 128), 256>>>(
            pos, rw + (size_t)i * DIM * DIM, rh, 2048, 1024, 1024, nullptr, 0);

        attn_kernel<<<dim3(16, 32), 256, ATTN_SMEM_BYTES>>>(wh, rh, rwb, rrb, av);

        mma_gemm<<<dim3(8, 16), 256>>>(
            av, ow + (size_t)i * DIM * DIM, tmp, 2048, 1024, 1024, nullptr, 0);
        ln_kernel<<<2048, 256>>>(tmp, core, ln1g + i * DIM, ln1b + i * DIM, core2, nullptr);

        mma_gemm<<<dim3(8, 16), 256>>>(
            core2, fw1 + (size_t)i * DIM * DIM, ff, 2048, 1024, 1024, fb1 + i * DIM, 1);
        mma_gemm<<<dim3(8, 16), 256>>>(
            ff, fw2 + (size_t)i * DIM * DIM, tmp, 2048, 1024, 1024, fb2 + i * DIM, 0);
        ln_kernel<<<2048, 256>>>(tmp, core2, ln2g + i * DIM, ln2b + i * DIM, core,
                                 out_mems ? out_mems + (size_t)(i + 1) * NE : nullptr);
    }
    copy_kernel<<<CB, 256>>>(out, core, C4);
}

// round 6
// speedup vs baseline: 3.1010x; 1.4042x over previous
#include <cuda_runtime.h>
#include <math.h>
#include <stdint.h>

#define L_Q   1024
#define BSZ   2
#define DIM   1024
#define NHEAD 16
#define DHEAD 64
#define NLAY  4
#define MLEN  1024
#define KLEN  2048
#define NE    (L_Q*BSZ*DIM)   /* 2097152 floats per (L,B,D) slab */

// ---------------- scratch (device globals; no allocation allowed) ----------------
__device__ float g_cat[(size_t)KLEN*BSZ*DIM];        // 16 MB
__device__ float g_wheads[(size_t)KLEN*BSZ*3*DIM];   // 50 MB
__device__ float g_pos[(size_t)KLEN*DIM];            // 8 MB
__device__ float g_rhead[(size_t)KLEN*DIM];          // 8 MB
__device__ float g_attnvec[NE];
__device__ float g_tmp[NE];
__device__ float g_core[NE];
__device__ float g_core2[NE];
__device__ float g_ff[NE];

// ---------------- simple float4 copy ----------------
__global__ void copy_kernel(float* __restrict__ dst, const float* __restrict__ src, int n4) {
    int i = blockIdx.x * blockDim.x + threadIdx.x;
    if (i < n4) ((float4*)dst)[i] = ((const float4*)src)[i];
}

// ---------------- positional embedding ----------------
__global__ void pos_kernel(float* __restrict__ pos) {
    int idx = blockIdx.x * blockDim.x + threadIdx.x;
    if (idx >= KLEN * DIM) return;
    int j = idx >> 10;           // 0..2047
    int i = idx & 1023;          // 0..1023
    int t = i & 511;
    float x = (float)(2 * t) * (1.0f / 1024.0f);
    float invf = expf(-x * 9.210340371976184f);   // 10000^{-x}
    float arg = (float)(KLEN - 1 - j) * invf;
    pos[idx] = (i < 512) ? sinf(arg) : cosf(arg);
}

// ---------------- tf32 helpers ----------------
__device__ __forceinline__ uint32_t f2tf32(float f) {
    uint32_t u;
    asm("cvt.rna.tf32.f32 %0, %1;" : "=r"(u) : "f"(f));
    return u;
}
__device__ __forceinline__ void mma_tf32(float* c, const uint32_t* a, const uint32_t* b) {
    asm volatile(
        "mma.sync.aligned.m16n8k8.row.col.f32.tf32.tf32.f32 "
        "{%0,%1,%2,%3}, {%4,%5,%6,%7}, {%8,%9}, {%0,%1,%2,%3};"
        : "+f"(c[0]), "+f"(c[1]), "+f"(c[2]), "+f"(c[3])
        : "r"(a[0]), "r"(a[1]), "r"(a[2]), "r"(a[3]), "r"(b[0]), "r"(b[1]));
}

// ---------------- tf32 tensor-core GEMM: 128x128 block, K-tile 32 ----------------
__global__ __launch_bounds__(256) void mma_gemm(
    const float* __restrict__ A, const float* __restrict__ B, float* __restrict__ C,
    int M, int N, int K, const float* __restrict__ bias, int relu)
{
    __shared__ __align__(16) uint32_t As[4096];
    __shared__ __align__(16) uint32_t Bs[4096];

    const int tid = threadIdx.x;
    const int lane = tid & 31;
    const int w = tid >> 5;
    const int wr = w & 1;            // 0..1
    const int wc = w >> 1;           // 0..3
    const int bx = blockIdx.x, by = blockIdx.y;

    const int sar = tid >> 1;                 // A row 0..127
    const int sac = (tid & 1) << 4;           // A col base 0 or 16
    const int sbk = tid >> 3;                 // B k-row 0..31
    const int sbn = (tid & 7) << 4;           // B col base 0..112

    const float* Ag = A + (size_t)(by * 128 + sar) * K + sac;
    const float* Bg = B + (size_t)sbk * N + bx * 128 + sbn;

    float acc[4][4][4];
#pragma unroll
    for (int mi = 0; mi < 4; mi++)
#pragma unroll
        for (int ni = 0; ni < 4; ni++)
#pragma unroll
            for (int q = 0; q < 4; q++) acc[mi][ni][q] = 0.f;

    float4 pa[4], pb[4];
#pragma unroll
    for (int t = 0; t < 4; t++) {
        pa[t] = *(const float4*)(Ag + t * 4);
        pb[t] = *(const float4*)(Bg + (size_t)0 + t * 4);
    }

    for (int kt = 0; kt < K; kt += 32) {
        __syncthreads();
        {
            const int mb = sar >> 4;
            const int lbase = (sar & 7) << 2;
            const int rq = (sar >> 3) & 1;
#pragma unroll
            for (int t = 0; t < 4; t++) {
                const int c = sac + t * 4;
                const int ks = c >> 3;
                const int q = rq + 2 * ((c >> 2) & 1);
                uint32_t* dst = &As[(((ks * 8 + mb) * 32 + lbase) << 2) + q];
                const float* f = (const float*)&pa[t];
                dst[0]  = f2tf32(f[0]);
                dst[4]  = f2tf32(f[1]);
                dst[8]  = f2tf32(f[2]);
                dst[12] = f2tf32(f[3]);
            }
            const int ks = sbk >> 3;
            const int kq = (sbk >> 2) & 1;
            const int kt2 = (sbk & 3) << 1;
#pragma unroll
            for (int t = 0; t < 4; t++) {
                const int n = sbn + t * 4;
                const int nb = n >> 3;
                uint32_t* dst = &Bs[(((ks * 16 + nb) * 32 + ((n & 7) << 2)) << 1) + kt2 + kq];
                const float* f = (const float*)&pb[t];
                dst[0]  = f2tf32(f[0]);
                dst[8]  = f2tf32(f[1]);
                dst[16] = f2tf32(f[2]);
                dst[24] = f2tf32(f[3]);
            }
        }
        __syncthreads();

        if (kt + 32 < K) {
#pragma unroll
            for (int t = 0; t < 4; t++) {
                pa[t] = *(const float4*)(Ag + (kt + 32) + t * 4);
                pb[t] = *(const float4*)(Bg + (size_t)(kt + 32) * N + t * 4);
            }
        }

#pragma unroll
        for (int ks = 0; ks < 4; ks++) {
            uint32_t afr[4][4], bfr[4][2];
#pragma unroll
            for (int mi = 0; mi < 4; mi++) {
                const uint4 v = *(const uint4*)&As[(((ks * 8 + wr * 4 + mi) * 32 + lane) << 2)];
                afr[mi][0] = v.x; afr[mi][1] = v.y; afr[mi][2] = v.z; afr[mi][3] = v.w;
            }
#pragma unroll
            for (int ni = 0; ni < 4; ni++) {
                const uint2 v = *(const uint2*)&Bs[(((ks * 16 + wc * 4 + ni) * 32 + lane) << 1)];
                bfr[ni][0] = v.x; bfr[ni][1] = v.y;
            }
#pragma unroll
            for (int mi = 0; mi < 4; mi++)
#pragma unroll
                for (int ni = 0; ni < 4; ni++)
                    mma_tf32(acc[mi][ni], afr[mi], bfr[ni]);
        }
    }

    const int g = lane >> 2;
    const int t = lane & 3;
#pragma unroll
    for (int mi = 0; mi < 4; mi++) {
        const int r0 = by * 128 + wr * 64 + mi * 16 + g;
#pragma unroll
        for (int ni = 0; ni < 4; ni++) {
            const int c0 = bx * 128 + wc * 32 + ni * 8 + t * 2;
            float b0 = 0.f, b1 = 0.f;
            if (bias) { b0 = bias[c0]; b1 = bias[c0 + 1]; }
            float2 o0, o1;
            o0.x = acc[mi][ni][0] + b0; o0.y = acc[mi][ni][1] + b1;
            o1.x = acc[mi][ni][2] + b0; o1.y = acc[mi][ni][3] + b1;
            if (relu) {
                o0.x = fmaxf(o0.x, 0.f); o0.y = fmaxf(o0.y, 0.f);
                o1.x = fmaxf(o1.x, 0.f); o1.y = fmaxf(o1.y, 0.f);
            }
            *(float2*)&C[(size_t)r0 * N + c0] = o0;
            *(float2*)&C[(size_t)(r0 + 8) * N + c0] = o1;
        }
    }
}

// ---------------- tensor-core fused rel-attention ----------------
// 64q x 64k tiles; S = Qw@K^T (64x64), E = Qr@R^T (64x128) via tf32 mma;
// rel-shift read BD[i,j] = E[i, j-i+63] after smem roundtrip; PV via tf32 mma.
// 8 warps: rb = w>>1 (16-row block), ch = w&1 (column half).
// smem layout (floats):
//   sQw 64x65 tf32 | sQr 64x65 | sK 64x65 | sR 128x65 | sV 64x68 |
//   sS 64x68 f32   | sE 64x136 f32 | sP 64x68 tf32 | sM[64] sL[64] sA[64]
#define AT_QW 0
#define AT_QR 4160
#define AT_K  8320
#define AT_R  12480
#define AT_V  20800
#define AT_S  25152
#define AT_E  29504
#define AT_P  38208
#define AT_M  42560
#define AT_L  42624
#define AT_A  42688
#define ATTN2_SMEM_FLOATS 42752
#define ATTN2_SMEM_BYTES  (ATTN2_SMEM_FLOATS * 4)

__global__ __launch_bounds__(256) void attn_mma_kernel(
    const float* __restrict__ wh, const float* __restrict__ rh,
    const float* __restrict__ rwb, const float* __restrict__ rrb,
    float* __restrict__ av)
{
    extern __shared__ float smf[];
    uint32_t* sQw = (uint32_t*)(smf + AT_QW);
    uint32_t* sQr = (uint32_t*)(smf + AT_QR);
    uint32_t* sK  = (uint32_t*)(smf + AT_K);
    uint32_t* sR  = (uint32_t*)(smf + AT_R);
    uint32_t* sV  = (uint32_t*)(smf + AT_V);
    float*    sS  = smf + AT_S;
    float*    sE  = smf + AT_E;
    uint32_t* sP  = (uint32_t*)(smf + AT_P);
    float*    sM  = smf + AT_M;
    float*    sL  = smf + AT_L;
    float*    sA  = smf + AT_A;

    const int i0 = blockIdx.x << 6;
    const int bi = blockIdx.y >> 4;
    const int hn = blockIdx.y & 15;
    const int tid = threadIdx.x;
    const int lane = tid & 31;
    const int w = tid >> 5;
    const int rb = w >> 1;           // 0..3
    const int ch = w & 1;            // 0..1
    const int g = lane >> 2;         // 0..7
    const int t = lane & 3;          // 0..3
    const int hbase = hn << 6;

    // load Q tiles (bias folded), tf32
    for (int idx = tid; idx < 4096; idx += 256) {
        const int r = idx >> 6, kk = idx & 63;
        float qv = wh[((size_t)((MLEN + i0 + r) * BSZ + bi)) * 3072 + hbase + kk];
        sQw[r * 65 + kk] = f2tf32(qv + rwb[hbase + kk]);
        sQr[r * 65 + kk] = f2tf32(qv + rrb[hbase + kk]);
    }
    if (tid < 64) { sM[tid] = -3e38f; sL[tid] = 0.f; }

    float acc[4][4];   // PV accum frags
#pragma unroll
    for (int cb = 0; cb < 4; cb++)
#pragma unroll
        for (int q = 0; q < 4; q++) acc[cb][q] = 0.f;

    const int arow0 = (16 * rb + g) * 65;
    const int arow1 = (16 * rb + g + 8) * 65;
    const int nkt = 17 + (i0 >> 6);

    for (int kt = 0; kt < nkt; kt++) {
        const int j0 = kt << 6;
        __syncthreads();
        // ---- stage K, V, R (tf32) ----
        for (int idx = tid; idx < 4096; idx += 256) {
            const int r = idx >> 6, kk = idx & 63;
            const size_t base = ((size_t)((j0 + r) * BSZ + bi)) * 3072 + hbase + kk;
            sK[r * 65 + kk] = f2tf32(wh[base + 1024]);
            sV[r * 68 + kk] = f2tf32(wh[base + 2048]);
        }
        const int rbase = j0 + MLEN - 1 - i0 - 63;
        for (int idx = tid; idx < 127 * 64; idx += 256) {
            const int r = idx >> 6, kk = idx & 63;
            int rg = rbase + r;
            rg = rg < 0 ? 0 : (rg > KLEN - 1 ? KLEN - 1 : rg);
            sR[r * 65 + kk] = f2tf32(rh[(size_t)rg * DIM + hbase + kk]);
        }
        __syncthreads();

        // ---- S and E via mma ----
        float Sacc[4][4], Eacc[8][4];
#pragma unroll
        for (int cb = 0; cb < 4; cb++)
#pragma unroll
            for (int q = 0; q < 4; q++) Sacc[cb][q] = 0.f;
#pragma unroll
        for (int eb = 0; eb < 8; eb++)
#pragma unroll
            for (int q = 0; q < 4; q++) Eacc[eb][q] = 0.f;

#pragma unroll
        for (int ks = 0; ks < 8; ks++) {
            const int kc = ks * 8 + t;
            uint32_t aw[4], ar[4];
            aw[0] = sQw[arow0 + kc]; aw[1] = sQw[arow1 + kc];
            aw[2] = sQw[arow0 + kc + 4]; aw[3] = sQw[arow1 + kc + 4];
            ar[0] = sQr[arow0 + kc]; ar[1] = sQr[arow1 + kc];
            ar[2] = sQr[arow0 + kc + 4]; ar[3] = sQr[arow1 + kc + 4];
#pragma unroll
            for (int cb = 0; cb < 4; cb++) {
                const int kr = (8 * (ch * 4 + cb) + g) * 65 + kc;
                uint32_t b[2] = { sK[kr], sK[kr + 4] };
                mma_tf32(Sacc[cb], aw, b);
            }
#pragma unroll
            for (int eb = 0; eb < 8; eb++) {
                const int rr = (8 * (ch * 8 + eb) + g) * 65 + kc;
                uint32_t b[2] = { sR[rr], sR[rr + 4] };
                mma_tf32(Eacc[eb], ar, b);
            }
        }
        // write S, E to smem
#pragma unroll
        for (int cb = 0; cb < 4; cb++) {
            const int col = 8 * (ch * 4 + cb) + 2 * t;
            sS[(16 * rb + g) * 68 + col]     = Sacc[cb][0];
            sS[(16 * rb + g) * 68 + col + 1] = Sacc[cb][1];
            sS[(16 * rb + g + 8) * 68 + col]     = Sacc[cb][2];
            sS[(16 * rb + g + 8) * 68 + col + 1] = Sacc[cb][3];
        }
#pragma unroll
        for (int eb = 0; eb < 8; eb++) {
            const int col = 8 * (ch * 8 + eb) + 2 * t;
            sE[(16 * rb + g) * 136 + col]     = Eacc[eb][0];
            sE[(16 * rb + g) * 136 + col + 1] = Eacc[eb][1];
            sE[(16 * rb + g + 8) * 136 + col]     = Eacc[eb][2];
            sE[(16 * rb + g + 8) * 136 + col + 1] = Eacc[eb][3];
        }
        __syncthreads();

        // ---- online softmax: warp w owns rows w*8..w*8+7; lane quad per row ----
        {
            const int row = w * 8 + g;
            const int qi = i0 + row;
            float sarr[16];
            {
                const float4* srow = (const float4*)&sS[row * 68 + t * 16];
#pragma unroll
                for (int v4 = 0; v4 < 4; v4++) {
                    float4 s4 = srow[v4];
                    sarr[v4 * 4 + 0] = s4.x; sarr[v4 * 4 + 1] = s4.y;
                    sarr[v4 * 4 + 2] = s4.z; sarr[v4 * 4 + 3] = s4.w;
                }
            }
            const int ebase = row * 135 + t * 16 + 63;   // row*136 + (t*16 - row + 63)
            float tmax = -3e38f;
#pragma unroll
            for (int e = 0; e < 16; e++) {
                float vv = (sarr[e] + sE[ebase + e]) * 0.125f;
                if (j0 + t * 16 + e > MLEN + qi) vv = -3e38f;
                sarr[e] = vv;
                tmax = fmaxf(tmax, vv);
            }
            tmax = fmaxf(tmax, __shfl_xor_sync(0xffffffffu, tmax, 1));
            tmax = fmaxf(tmax, __shfl_xor_sync(0xffffffffu, tmax, 2));
            const float mold = sM[row];
            const float mnew = fmaxf(mold, tmax);
            float rsum = 0.f;
            uint32_t pb[16];
#pragma unroll
            for (int e = 0; e < 16; e++) {
                float p = __expf(sarr[e] - mnew);
                rsum += p;
                pb[e] = f2tf32(p);
            }
            rsum += __shfl_xor_sync(0xffffffffu, rsum, 1);
            rsum += __shfl_xor_sync(0xffffffffu, rsum, 2);
            if (t == 0) {
                const float al = __expf(mold - mnew);
                sM[row] = mnew;
                sA[row] = al;
                sL[row] = sL[row] * al + rsum;
            }
            uint4* pd = (uint4*)&sP[row * 68 + t * 16];
            pd[0] = make_uint4(pb[0], pb[1], pb[2], pb[3]);
            pd[1] = make_uint4(pb[4], pb[5], pb[6], pb[7]);
            pd[2] = make_uint4(pb[8], pb[9], pb[10], pb[11]);
            pd[3] = make_uint4(pb[12], pb[13], pb[14], pb[15]);
        }
        __syncthreads();

        // ---- rescale + P@V via mma ----
        {
            const float al0 = sA[16 * rb + g];
            const float al1 = sA[16 * rb + g + 8];
#pragma unroll
            for (int cb = 0; cb < 4; cb++) {
                acc[cb][0] *= al0; acc[cb][1] *= al0;
                acc[cb][2] *= al1; acc[cb][3] *= al1;
            }
            const int prow0 = (16 * rb + g) * 68;
            const int prow1 = (16 * rb + g + 8) * 68;
#pragma unroll
            for (int ks = 0; ks < 8; ks++) {
                const int kc = ks * 8 + t;
                uint32_t a[4] = { sP[prow0 + kc], sP[prow1 + kc],
                                  sP[prow0 + kc + 4], sP[prow1 + kc + 4] };
#pragma unroll
                for (int cb = 0; cb < 4; cb++) {
                    const int col = 8 * (ch * 4 + cb) + g;
                    uint32_t b[2] = { sV[(ks * 8 + t) * 68 + col],
                                      sV[(ks * 8 + t + 4) * 68 + col] };
                    mma_tf32(acc[cb], a, b);
                }
            }
        }
    }

    // ---- finalize ----
    const float linv0 = 1.f / sL[16 * rb + g];
    const float linv1 = 1.f / sL[16 * rb + g + 8];
    const int r0 = i0 + 16 * rb + g;
#pragma unroll
    for (int cb = 0; cb < 4; cb++) {
        const int col = hbase + 8 * (ch * 4 + cb) + 2 * t;
        float2 o0, o1;
        o0.x = acc[cb][0] * linv0; o0.y = acc[cb][1] * linv0;
        o1.x = acc[cb][2] * linv1; o1.y = acc[cb][3] * linv1;
        *(float2*)&av[((size_t)(r0 * BSZ + bi)) * DIM + col] = o0;
        *(float2*)&av[((size_t)((r0 + 8) * BSZ + bi)) * DIM + col] = o1;
    }
}

// ---------------- residual + layernorm (row per block) ----------------
__global__ __launch_bounds__(256) void ln_kernel(
    const float* __restrict__ x, const float* __restrict__ res,
    const float* __restrict__ g, const float* __restrict__ b,
    float* __restrict__ out1, float* __restrict__ out2)
{
    const int row = blockIdx.x;
    const int tid = threadIdx.x;
    float4 xv = *(const float4*)(x + (size_t)row * DIM + tid * 4);
    float4 rv = *(const float4*)(res + (size_t)row * DIM + tid * 4);
    float v0 = xv.x + rv.x, v1 = xv.y + rv.y, v2 = xv.z + rv.z, v3 = xv.w + rv.w;
    float s = v0 + v1 + v2 + v3;
    float q = v0 * v0 + v1 * v1 + v2 * v2 + v3 * v3;
#pragma unroll
    for (int off = 16; off > 0; off >>= 1) {
        s += __shfl_xor_sync(0xffffffffu, s, off);
        q += __shfl_xor_sync(0xffffffffu, q, off);
    }
    __shared__ float sb[8], qb[8];
    const int w = tid >> 5, lane = tid & 31;
    if (lane == 0) { sb[w] = s; qb[w] = q; }
    __syncthreads();
    if (w == 0) {
        float s2 = (lane < 8) ? sb[lane] : 0.f;
        float q2 = (lane < 8) ? qb[lane] : 0.f;
#pragma unroll
        for (int off = 4; off > 0; off >>= 1) {
            s2 += __shfl_xor_sync(0xffffffffu, s2, off);
            q2 += __shfl_xor_sync(0xffffffffu, q2, off);
        }
        if (lane == 0) { sb[0] = s2; qb[0] = q2; }
    }
    __syncthreads();
    const float mean = sb[0] * (1.0f / DIM);
    const float var  = qb[0] * (1.0f / DIM) - mean * mean;
    const float rstd = rsqrtf(var + 1e-5f);
    float4 gv = *(const float4*)(g + tid * 4);
    float4 bv = *(const float4*)(b + tid * 4);
    float4 o;
    o.x = (v0 - mean) * rstd * gv.x + bv.x;
    o.y = (v1 - mean) * rstd * gv.y + bv.y;
    o.z = (v2 - mean) * rstd * gv.z + bv.z;
    o.w = (v3 - mean) * rstd * gv.w + bv.w;
    *(float4*)(out1 + (size_t)row * DIM + tid * 4) = o;
    if (out2) *(float4*)(out2 + (size_t)row * DIM + tid * 4) = o;
}

// ---------------- host orchestration ----------------
extern "C" void kernel_launch(void* const* d_in, const int* in_sizes, int n_in,
                              void* d_out, int out_size) {
    const float* mems = (const float*)d_in[0];
    const float* raw  = (const float*)d_in[1];
    /* d_in[2] = attention_mask: analytic, ignored */
    const float* rwb  = (const float*)d_in[3];
    const float* rrb  = (const float*)d_in[4];
    const float* qkvw = (const float*)d_in[5];
    const float* rw   = (const float*)d_in[6];
    const float* ow   = (const float*)d_in[7];
    const float* ln1g = (const float*)d_in[8];
    const float* ln1b = (const float*)d_in[9];
    const float* fw1  = (const float*)d_in[10];
    const float* fb1  = (const float*)d_in[11];
    const float* fw2  = (const float*)d_in[12];
    const float* fb2  = (const float*)d_in[13];
    const float* ln2g = (const float*)d_in[14];
    const float* ln2b = (const float*)d_in[15];
    float* out = (float*)d_out;

    const bool full_out = out_size >= (NLAY + 2) * NE;   // core + new_mems(5 slabs)
    float* out_mems = full_out ? out + NE : nullptr;

    float *cat, *wh, *pos, *rh, *av, *tmp, *core, *core2, *ff;
    cudaGetSymbolAddress((void**)&cat,  g_cat);
    cudaGetSymbolAddress((void**)&wh,   g_wheads);
    cudaGetSymbolAddress((void**)&pos,  g_pos);
    cudaGetSymbolAddress((void**)&rh,   g_rhead);
    cudaGetSymbolAddress((void**)&av,   g_attnvec);
    cudaGetSymbolAddress((void**)&tmp,  g_tmp);
    cudaGetSymbolAddress((void**)&core, g_core);
    cudaGetSymbolAddress((void**)&core2,g_core2);
    cudaGetSymbolAddress((void**)&ff,   g_ff);

    cudaFuncSetAttribute((const void*)attn_mma_kernel,
                         cudaFuncAttributeMaxDynamicSharedMemorySize, ATTN2_SMEM_BYTES);

    const int C4 = NE / 4;               // float4 count per slab
    const int CB = (C4 + 255) / 256;

    copy_kernel<<<CB, 256>>>(core, raw, C4);
    if (out_mems) copy_kernel<<<CB, 256>>>(out_mems, raw, C4);
    pos_kernel<<<(KLEN * DIM + 255) / 256, 256>>>(pos);

    for (int i = 0; i < NLAY; i++) {
        copy_kernel<<<CB, 256>>>(cat, mems + (size_t)i * NE, C4);
        copy_kernel<<<CB, 256>>>(cat + NE, core, C4);

        mma_gemm<<<dim3(3072 / 128, 4096 / 128), 256>>>(
            cat, qkvw + (size_t)i * DIM * 3 * DIM, wh, 4096, 3072, 1024, nullptr, 0);
        mma_gemm<<<dim3(1024 / 128, 2048 / 128), 256>>>(
            pos, rw + (size_t)i * DIM * DIM, rh, 2048, 1024, 1024, nullptr, 0);

        attn_mma_kernel<<<dim3(16, 32), 256, ATTN2_SMEM_BYTES>>>(wh, rh, rwb, rrb, av);

        mma_gemm<<<dim3(8, 16), 256>>>(
            av, ow + (size_t)i * DIM * DIM, tmp, 2048, 1024, 1024, nullptr, 0);
        ln_kernel<<<2048, 256>>>(tmp, core, ln1g + i * DIM, ln1b + i * DIM, core2, nullptr);

        mma_gemm<<<dim3(8, 16), 256>>>(
            core2, fw1 + (size_t)i * DIM * DIM, ff, 2048, 1024, 1024, fb1 + i * DIM, 1);
        mma_gemm<<<dim3(8, 16), 256>>>(
            ff, fw2 + (size_t)i * DIM * DIM, tmp, 2048, 1024, 1024, fb2 + i * DIM, 0);
        ln_kernel<<<2048, 256>>>(tmp, core2, ln2g + i * DIM, ln2b + i * DIM, core,
                                 out_mems ? out_mems + (size_t)(i + 1) * NE : nullptr);
    }
    copy_kernel<<<CB, 256>>>(out, core, C4);
}

// round 7
// speedup vs baseline: 4.7815x; 1.5419x over previous
#include <cuda_runtime.h>
#include <math.h>
#include <stdint.h>

#define L_Q   1024
#define BSZ   2
#define DIM   1024
#define NHEAD 16
#define DHEAD 64
#define NLAY  4
#define MLEN  1024
#define KLEN  2048
#define NE    (L_Q*BSZ*DIM)   /* 2097152 floats per (L,B,D) slab */

// ---------------- scratch (device globals; no allocation allowed) ----------------
__device__ float g_cat[(size_t)KLEN*BSZ*DIM];        // 16 MB
__device__ float g_wheads[(size_t)KLEN*BSZ*3*DIM];   // 50 MB
__device__ float g_pos[(size_t)KLEN*DIM];            // 8 MB
__device__ float g_rhead[(size_t)KLEN*DIM];          // 8 MB
__device__ float g_attnvec[NE];
__device__ float g_tmp[NE];
__device__ float g_core[NE];
__device__ float g_core2[NE];
__device__ float g_ff[NE];

// ---------------- simple float4 copy ----------------
__global__ void copy_kernel(float* __restrict__ dst, const float* __restrict__ src, int n4) {
    int i = blockIdx.x * blockDim.x + threadIdx.x;
    if (i < n4) ((float4*)dst)[i] = ((const float4*)src)[i];
}

// ---------------- positional embedding ----------------
__global__ void pos_kernel(float* __restrict__ pos) {
    int idx = blockIdx.x * blockDim.x + threadIdx.x;
    if (idx >= KLEN * DIM) return;
    int j = idx >> 10;           // 0..2047
    int i = idx & 1023;          // 0..1023
    int t = i & 511;
    float x = (float)(2 * t) * (1.0f / 1024.0f);
    float invf = expf(-x * 9.210340371976184f);   // 10000^{-x}
    float arg = (float)(KLEN - 1 - j) * invf;
    pos[idx] = (i < 512) ? sinf(arg) : cosf(arg);
}

// ---------------- tf32 helpers ----------------
__device__ __forceinline__ uint32_t f2tf32(float f) {
    uint32_t u;
    asm("cvt.rna.tf32.f32 %0, %1;" : "=r"(u) : "f"(f));
    return u;
}
__device__ __forceinline__ uint4 cvt4(float4 v) {
    return make_uint4(f2tf32(v.x), f2tf32(v.y), f2tf32(v.z), f2tf32(v.w));
}
__device__ __forceinline__ void mma_tf32(float* c, const uint32_t* a, const uint32_t* b) {
    asm volatile(
        "mma.sync.aligned.m16n8k8.row.col.f32.tf32.tf32.f32 "
        "{%0,%1,%2,%3}, {%4,%5,%6,%7}, {%8,%9}, {%0,%1,%2,%3};"
        : "+f"(c[0]), "+f"(c[1]), "+f"(c[2]), "+f"(c[3])
        : "r"(a[0]), "r"(a[1]), "r"(a[2]), "r"(a[3]), "r"(b[0]), "r"(b[1]));
}

// ---------------- tf32 tensor-core GEMM: 128x128 block, K-tile 32 ----------------
// Generalized strides: A[M,K] lda, B[K,N] ldb, C[M,N] ldc (row-major).
__global__ __launch_bounds__(256) void mma_gemm(
    const float* __restrict__ A, const float* __restrict__ B, float* __restrict__ C,
    int M, int N, int K, int lda, int ldb, int ldc,
    const float* __restrict__ bias, int relu)
{
    __shared__ __align__(16) uint32_t As[4096];
    __shared__ __align__(16) uint32_t Bs[4096];

    const int tid = threadIdx.x;
    const int lane = tid & 31;
    const int w = tid >> 5;
    const int wr = w & 1;            // 0..1
    const int wc = w >> 1;           // 0..3
    const int bx = blockIdx.x, by = blockIdx.y;

    const int sar = tid >> 1;                 // A row 0..127
    const int sac = (tid & 1) << 4;           // A col base 0 or 16
    const int sbk = tid >> 3;                 // B k-row 0..31
    const int sbn = (tid & 7) << 4;           // B col base 0..112

    const float* Ag = A + (size_t)(by * 128 + sar) * lda + sac;
    const float* Bg = B + (size_t)sbk * ldb + bx * 128 + sbn;

    float acc[4][4][4];
#pragma unroll
    for (int mi = 0; mi < 4; mi++)
#pragma unroll
        for (int ni = 0; ni < 4; ni++)
#pragma unroll
            for (int q = 0; q < 4; q++) acc[mi][ni][q] = 0.f;

    float4 pa[4], pb[4];
#pragma unroll
    for (int t = 0; t < 4; t++) {
        pa[t] = *(const float4*)(Ag + t * 4);
        pb[t] = *(const float4*)(Bg + t * 4);
    }

    for (int kt = 0; kt < K; kt += 32) {
        __syncthreads();
        {
            const int mb = sar >> 4;
            const int lbase = (sar & 7) << 2;
            const int rq = (sar >> 3) & 1;
#pragma unroll
            for (int t = 0; t < 4; t++) {
                const int c = sac + t * 4;
                const int ks = c >> 3;
                const int q = rq + 2 * ((c >> 2) & 1);
                uint32_t* dst = &As[(((ks * 8 + mb) * 32 + lbase) << 2) + q];
                const float* f = (const float*)&pa[t];
                dst[0]  = f2tf32(f[0]);
                dst[4]  = f2tf32(f[1]);
                dst[8]  = f2tf32(f[2]);
                dst[12] = f2tf32(f[3]);
            }
            const int ks = sbk >> 3;
            const int kq = (sbk >> 2) & 1;
            const int kt2 = (sbk & 3) << 1;
#pragma unroll
            for (int t = 0; t < 4; t++) {
                const int n = sbn + t * 4;
                const int nb = n >> 3;
                uint32_t* dst = &Bs[(((ks * 16 + nb) * 32 + ((n & 7) << 2)) << 1) + kt2 + kq];
                const float* f = (const float*)&pb[t];
                dst[0]  = f2tf32(f[0]);
                dst[8]  = f2tf32(f[1]);
                dst[16] = f2tf32(f[2]);
                dst[24] = f2tf32(f[3]);
            }
        }
        __syncthreads();

        if (kt + 32 < K) {
#pragma unroll
            for (int t = 0; t < 4; t++) {
                pa[t] = *(const float4*)(Ag + (kt + 32) + t * 4);
                pb[t] = *(const float4*)(Bg + (size_t)(kt + 32) * ldb + t * 4);
            }
        }

#pragma unroll
        for (int ks = 0; ks < 4; ks++) {
            uint32_t afr[4][4], bfr[4][2];
#pragma unroll
            for (int mi = 0; mi < 4; mi++) {
                const uint4 v = *(const uint4*)&As[(((ks * 8 + wr * 4 + mi) * 32 + lane) << 2)];
                afr[mi][0] = v.x; afr[mi][1] = v.y; afr[mi][2] = v.z; afr[mi][3] = v.w;
            }
#pragma unroll
            for (int ni = 0; ni < 4; ni++) {
                const uint2 v = *(const uint2*)&Bs[(((ks * 16 + wc * 4 + ni) * 32 + lane) << 1)];
                bfr[ni][0] = v.x; bfr[ni][1] = v.y;
            }
#pragma unroll
            for (int mi = 0; mi < 4; mi++)
#pragma unroll
                for (int ni = 0; ni < 4; ni++)
                    mma_tf32(acc[mi][ni], afr[mi], bfr[ni]);
        }
    }

    const int g = lane >> 2;
    const int t = lane & 3;
#pragma unroll
    for (int mi = 0; mi < 4; mi++) {
        const int r0 = by * 128 + wr * 64 + mi * 16 + g;
#pragma unroll
        for (int ni = 0; ni < 4; ni++) {
            const int c0 = bx * 128 + wc * 32 + ni * 8 + t * 2;
            float b0 = 0.f, b1 = 0.f;
            if (bias) { b0 = bias[c0]; b1 = bias[c0 + 1]; }
            float2 o0, o1;
            o0.x = acc[mi][ni][0] + b0; o0.y = acc[mi][ni][1] + b1;
            o1.x = acc[mi][ni][2] + b0; o1.y = acc[mi][ni][3] + b1;
            if (relu) {
                o0.x = fmaxf(o0.x, 0.f); o0.y = fmaxf(o0.y, 0.f);
                o1.x = fmaxf(o1.x, 0.f); o1.y = fmaxf(o1.y, 0.f);
            }
            *(float2*)&C[(size_t)r0 * ldc + c0] = o0;
            *(float2*)&C[(size_t)(r0 + 8) * ldc + c0] = o1;
        }
    }
}

// ---------------- tensor-core fused rel-attention (pitch-68, conflict-free) ----
// 64q x 64k tiles; S = Qw@K^T, E = Qr@R^T via tf32 mma; rel-shift band read;
// PV via tf32 mma. 8 warps: rb=w>>1 (16-row block), ch=w&1 (column half).
#define AT_QW 0                     /* 64x68 tf32 */
#define AT_QR 4352
#define AT_K  8704
#define AT_R  13056                 /* 128x68 (127 used) */
#define AT_V  21760
#define AT_S  26112                 /* 64x68 f32 */
#define AT_E  30464                 /* 64x136 f32 */
#define AT_P  39168                 /* 64x68 tf32 */
#define AT_M  43520
#define AT_L  43584
#define AT_A  43648
#define ATTN2_SMEM_FLOATS 43712
#define ATTN2_SMEM_BYTES  (ATTN2_SMEM_FLOATS * 4)

__global__ __launch_bounds__(256) void attn_mma_kernel(
    const float* __restrict__ wh, const float* __restrict__ rh,
    const float* __restrict__ rwb, const float* __restrict__ rrb,
    float* __restrict__ av)
{
    extern __shared__ float smf[];
    uint32_t* sQw = (uint32_t*)(smf + AT_QW);
    uint32_t* sQr = (uint32_t*)(smf + AT_QR);
    uint32_t* sK  = (uint32_t*)(smf + AT_K);
    uint32_t* sR  = (uint32_t*)(smf + AT_R);
    uint32_t* sV  = (uint32_t*)(smf + AT_V);
    float*    sS  = smf + AT_S;
    float*    sE  = smf + AT_E;
    uint32_t* sP  = (uint32_t*)(smf + AT_P);
    float*    sM  = smf + AT_M;
    float*    sL  = smf + AT_L;
    float*    sA  = smf + AT_A;

    const int i0 = (15 - blockIdx.x) << 6;   // heaviest q-tile first
    const int bi = blockIdx.y >> 4;
    const int hn = blockIdx.y & 15;
    const int tid = threadIdx.x;
    const int lane = tid & 31;
    const int w = tid >> 5;
    const int rb = w >> 1;           // 0..3
    const int ch = w & 1;            // 0..1
    const int g = lane >> 2;         // 0..7
    const int t = lane & 3;          // 0..3
    const int hbase = hn << 6;

    // staging lane coords (float4 granularity)
    const int svr = tid >> 4;             // row 0..15 base (of 64, via +u*16)
    const int svc = (tid & 15) << 2;      // col 0,4,..,60

    // ---- load Q tiles (bias folded), vectorized ----
    {
        float4 w4 = *(const float4*)&rwb[hbase + svc];
        float4 r4 = *(const float4*)&rrb[hbase + svc];
#pragma unroll
        for (int u = 0; u < 4; u++) {
            const int r = svr + u * 16;
            const size_t base = ((size_t)((MLEN + i0 + r) * BSZ + bi)) * 3072 + hbase + svc;
            float4 q4 = *(const float4*)&wh[base];
            float4 aw = make_float4(q4.x + w4.x, q4.y + w4.y, q4.z + w4.z, q4.w + w4.w);
            float4 ar = make_float4(q4.x + r4.x, q4.y + r4.y, q4.z + r4.z, q4.w + r4.w);
            *(uint4*)&sQw[r * 68 + svc] = cvt4(aw);
            *(uint4*)&sQr[r * 68 + svc] = cvt4(ar);
        }
    }
    if (tid < 64) { sM[tid] = -3e38f; sL[tid] = 0.f; }

    float acc[4][4];   // PV accum frags
#pragma unroll
    for (int cb = 0; cb < 4; cb++)
#pragma unroll
        for (int q = 0; q < 4; q++) acc[cb][q] = 0.f;

    const int arow0 = (16 * rb + g) * 68;
    const int arow1 = (16 * rb + g + 8) * 68;
    const int nkt = 17 + (i0 >> 6);

    // K/V prefetch registers for tile 0
    float4 pk[4], pv[4];
#pragma unroll
    for (int u = 0; u < 4; u++) {
        const int r = svr + u * 16;
        const size_t base = ((size_t)(r * BSZ + bi)) * 3072 + hbase + svc;
        pk[u] = *(const float4*)&wh[base + 1024];
        pv[u] = *(const float4*)&wh[base + 2048];
    }

    for (int kt = 0; kt < nkt; kt++) {
        const int j0 = kt << 6;
        __syncthreads();
        // ---- store prefetched K/V; stage R directly ----
#pragma unroll
        for (int u = 0; u < 4; u++) {
            const int r = svr + u * 16;
            *(uint4*)&sK[r * 68 + svc] = cvt4(pk[u]);
            *(uint4*)&sV[r * 68 + svc] = cvt4(pv[u]);
        }
        const int rbase = j0 + MLEN - 1 - i0 - 63;
#pragma unroll
        for (int u = 0; u < 8; u++) {
            const int idx = tid + u * 256;
            if (idx < 2032) {
                const int r = idx >> 4, c4 = (idx & 15) << 2;
                int rg = rbase + r;
                rg = rg < 0 ? 0 : (rg > KLEN - 1 ? KLEN - 1 : rg);
                const float4 v = *(const float4*)&rh[(size_t)rg * DIM + hbase + c4];
                *(uint4*)&sR[r * 68 + c4] = cvt4(v);
            }
        }
        __syncthreads();

        // ---- prefetch next tile's K/V (overlaps mma below) ----
        if (kt + 1 < nkt) {
#pragma unroll
            for (int u = 0; u < 4; u++) {
                const int r = svr + u * 16;
                const size_t base = ((size_t)(((j0 + 64) + r) * BSZ + bi)) * 3072 + hbase + svc;
                pk[u] = *(const float4*)&wh[base + 1024];
                pv[u] = *(const float4*)&wh[base + 2048];
            }
        }

        // ---- S and E via mma ----
        float Sacc[4][4], Eacc[8][4];
#pragma unroll
        for (int cb = 0; cb < 4; cb++)
#pragma unroll
            for (int q = 0; q < 4; q++) Sacc[cb][q] = 0.f;
#pragma unroll
        for (int eb = 0; eb < 8; eb++)
#pragma unroll
            for (int q = 0; q < 4; q++) Eacc[eb][q] = 0.f;

#pragma unroll
        for (int ks = 0; ks < 8; ks++) {
            const int kc = ks * 8 + t;
            uint32_t aw[4], ar[4];
            aw[0] = sQw[arow0 + kc]; aw[1] = sQw[arow1 + kc];
            aw[2] = sQw[arow0 + kc + 4]; aw[3] = sQw[arow1 + kc + 4];
            ar[0] = sQr[arow0 + kc]; ar[1] = sQr[arow1 + kc];
            ar[2] = sQr[arow0 + kc + 4]; ar[3] = sQr[arow1 + kc + 4];
#pragma unroll
            for (int cb = 0; cb < 4; cb++) {
                const int kr = (8 * (ch * 4 + cb) + g) * 68 + kc;
                uint32_t b[2] = { sK[kr], sK[kr + 4] };
                mma_tf32(Sacc[cb], aw, b);
            }
#pragma unroll
            for (int eb = 0; eb < 8; eb++) {
                const int rr = (8 * (ch * 8 + eb) + g) * 68 + kc;
                uint32_t b[2] = { sR[rr], sR[rr + 4] };
                mma_tf32(Eacc[eb], ar, b);
            }
        }
        // write S, E to smem (float2 stores)
#pragma unroll
        for (int cb = 0; cb < 4; cb++) {
            const int col = 8 * (ch * 4 + cb) + 2 * t;
            *(float2*)&sS[(16 * rb + g) * 68 + col]     = make_float2(Sacc[cb][0], Sacc[cb][1]);
            *(float2*)&sS[(16 * rb + g + 8) * 68 + col] = make_float2(Sacc[cb][2], Sacc[cb][3]);
        }
#pragma unroll
        for (int eb = 0; eb < 8; eb++) {
            const int col = 8 * (ch * 8 + eb) + 2 * t;
            *(float2*)&sE[(16 * rb + g) * 136 + col]     = make_float2(Eacc[eb][0], Eacc[eb][1]);
            *(float2*)&sE[(16 * rb + g + 8) * 136 + col] = make_float2(Eacc[eb][2], Eacc[eb][3]);
        }
        __syncthreads();

        // ---- online softmax: warp w owns rows w*8..w*8+7; lane quad per row ----
        {
            const int row = w * 8 + g;
            const int qi = i0 + row;
            float sarr[16];
            {
                const float4* srow = (const float4*)&sS[row * 68 + t * 16];
#pragma unroll
                for (int v4 = 0; v4 < 4; v4++) {
                    float4 s4 = srow[v4];
                    sarr[v4 * 4 + 0] = s4.x; sarr[v4 * 4 + 1] = s4.y;
                    sarr[v4 * 4 + 2] = s4.z; sarr[v4 * 4 + 3] = s4.w;
                }
            }
            const int ebase = row * 135 + t * 16 + 63;   // row*136 + (t*16 - row + 63)
            float tmax = -3e38f;
#pragma unroll
            for (int e = 0; e < 16; e++) {
                float vv = (sarr[e] + sE[ebase + e]) * 0.125f;
                if (j0 + t * 16 + e > MLEN + qi) vv = -3e38f;
                sarr[e] = vv;
                tmax = fmaxf(tmax, vv);
            }
            tmax = fmaxf(tmax, __shfl_xor_sync(0xffffffffu, tmax, 1));
            tmax = fmaxf(tmax, __shfl_xor_sync(0xffffffffu, tmax, 2));
            const float mold = sM[row];
            const float mnew = fmaxf(mold, tmax);
            float rsum = 0.f;
            uint32_t pb[16];
#pragma unroll
            for (int e = 0; e < 16; e++) {
                float p = __expf(sarr[e] - mnew);
                rsum += p;
                pb[e] = f2tf32(p);
            }
            rsum += __shfl_xor_sync(0xffffffffu, rsum, 1);
            rsum += __shfl_xor_sync(0xffffffffu, rsum, 2);
            if (t == 0) {
                const float al = __expf(mold - mnew);
                sM[row] = mnew;
                sA[row] = al;
                sL[row] = sL[row] * al + rsum;
            }
            uint4* pd = (uint4*)&sP[row * 68 + t * 16];
            pd[0] = make_uint4(pb[0], pb[1], pb[2], pb[3]);
            pd[1] = make_uint4(pb[4], pb[5], pb[6], pb[7]);
            pd[2] = make_uint4(pb[8], pb[9], pb[10], pb[11]);
            pd[3] = make_uint4(pb[12], pb[13], pb[14], pb[15]);
        }
        __syncthreads();

        // ---- rescale + P@V via mma ----
        {
            const float al0 = sA[16 * rb + g];
            const float al1 = sA[16 * rb + g + 8];
#pragma unroll
            for (int cb = 0; cb < 4; cb++) {
                acc[cb][0] *= al0; acc[cb][1] *= al0;
                acc[cb][2] *= al1; acc[cb][3] *= al1;
            }
            const int prow0 = (16 * rb + g) * 68;
            const int prow1 = (16 * rb + g + 8) * 68;
#pragma unroll
            for (int ks = 0; ks < 8; ks++) {
                const int kc = ks * 8 + t;
                uint32_t a[4] = { sP[prow0 + kc], sP[prow1 + kc],
                                  sP[prow0 + kc + 4], sP[prow1 + kc + 4] };
#pragma unroll
                for (int cb = 0; cb < 4; cb++) {
                    const int col = 8 * (ch * 4 + cb) + g;
                    uint32_t b[2] = { sV[(ks * 8 + t) * 68 + col],
                                      sV[(ks * 8 + t + 4) * 68 + col] };
                    mma_tf32(acc[cb], a, b);
                }
            }
        }
    }

    // ---- finalize ----
    const float linv0 = 1.f / sL[16 * rb + g];
    const float linv1 = 1.f / sL[16 * rb + g + 8];
    const int r0 = i0 + 16 * rb + g;
#pragma unroll
    for (int cb = 0; cb < 4; cb++) {
        const int col = hbase + 8 * (ch * 4 + cb) + 2 * t;
        float2 o0, o1;
        o0.x = acc[cb][0] * linv0; o0.y = acc[cb][1] * linv0;
        o1.x = acc[cb][2] * linv1; o1.y = acc[cb][3] * linv1;
        *(float2*)&av[((size_t)(r0 * BSZ + bi)) * DIM + col] = o0;
        *(float2*)&av[((size_t)((r0 + 8) * BSZ + bi)) * DIM + col] = o1;
    }
}

// ---------------- residual + layernorm (row per block) ----------------
__global__ __launch_bounds__(256) void ln_kernel(
    const float* __restrict__ x, const float* __restrict__ res,
    const float* __restrict__ g, const float* __restrict__ b,
    float* __restrict__ out1, float* __restrict__ out2)
{
    const int row = blockIdx.x;
    const int tid = threadIdx.x;
    float4 xv = *(const float4*)(x + (size_t)row * DIM + tid * 4);
    float4 rv = *(const float4*)(res + (size_t)row * DIM + tid * 4);
    float v0 = xv.x + rv.x, v1 = xv.y + rv.y, v2 = xv.z + rv.z, v3 = xv.w + rv.w;
    float s = v0 + v1 + v2 + v3;
    float q = v0 * v0 + v1 * v1 + v2 * v2 + v3 * v3;
#pragma unroll
    for (int off = 16; off > 0; off >>= 1) {
        s += __shfl_xor_sync(0xffffffffu, s, off);
        q += __shfl_xor_sync(0xffffffffu, q, off);
    }
    __shared__ float sb[8], qb[8];
    const int w = tid >> 5, lane = tid & 31;
    if (lane == 0) { sb[w] = s; qb[w] = q; }
    __syncthreads();
    if (w == 0) {
        float s2 = (lane < 8) ? sb[lane] : 0.f;
        float q2 = (lane < 8) ? qb[lane] : 0.f;
#pragma unroll
        for (int off = 4; off > 0; off >>= 1) {
            s2 += __shfl_xor_sync(0xffffffffu, s2, off);
            q2 += __shfl_xor_sync(0xffffffffu, q2, off);
        }
        if (lane == 0) { sb[0] = s2; qb[0] = q2; }
    }
    __syncthreads();
    const float mean = sb[0] * (1.0f / DIM);
    const float var  = qb[0] * (1.0f / DIM) - mean * mean;
    const float rstd = rsqrtf(var + 1e-5f);
    float4 gv = *(const float4*)(g + tid * 4);
    float4 bv = *(const float4*)(b + tid * 4);
    float4 o;
    o.x = (v0 - mean) * rstd * gv.x + bv.x;
    o.y = (v1 - mean) * rstd * gv.y + bv.y;
    o.z = (v2 - mean) * rstd * gv.z + bv.z;
    o.w = (v3 - mean) * rstd * gv.w + bv.w;
    *(float4*)(out1 + (size_t)row * DIM + tid * 4) = o;
    if (out2) *(float4*)(out2 + (size_t)row * DIM + tid * 4) = o;
}

// ---------------- host orchestration ----------------
extern "C" void kernel_launch(void* const* d_in, const int* in_sizes, int n_in,
                              void* d_out, int out_size) {
    const float* mems = (const float*)d_in[0];
    const float* raw  = (const float*)d_in[1];
    /* d_in[2] = attention_mask: analytic, ignored */
    const float* rwb  = (const float*)d_in[3];
    const float* rrb  = (const float*)d_in[4];
    const float* qkvw = (const float*)d_in[5];
    const float* rw   = (const float*)d_in[6];
    const float* ow   = (const float*)d_in[7];
    const float* ln1g = (const float*)d_in[8];
    const float* ln1b = (const float*)d_in[9];
    const float* fw1  = (const float*)d_in[10];
    const float* fb1  = (const float*)d_in[11];
    const float* fw2  = (const float*)d_in[12];
    const float* fb2  = (const float*)d_in[13];
    const float* ln2g = (const float*)d_in[14];
    const float* ln2b = (const float*)d_in[15];
    float* out = (float*)d_out;

    const bool full_out = out_size >= (NLAY + 2) * NE;   // core + new_mems(5 slabs)
    float* out_mems = full_out ? out + NE : nullptr;

    float *cat, *wh, *pos, *rh, *av, *tmp, *core, *core2, *ff;
    cudaGetSymbolAddress((void**)&cat,  g_cat);
    cudaGetSymbolAddress((void**)&wh,   g_wheads);
    cudaGetSymbolAddress((void**)&pos,  g_pos);
    cudaGetSymbolAddress((void**)&rh,   g_rhead);
    cudaGetSymbolAddress((void**)&av,   g_attnvec);
    cudaGetSymbolAddress((void**)&tmp,  g_tmp);
    cudaGetSymbolAddress((void**)&core, g_core);
    cudaGetSymbolAddress((void**)&core2,g_core2);
    cudaGetSymbolAddress((void**)&ff,   g_ff);

    cudaFuncSetAttribute((const void*)attn_mma_kernel,
                         cudaFuncAttributeMaxDynamicSharedMemorySize, ATTN2_SMEM_BYTES);

    const int C4 = NE / 4;               // float4 count per slab
    const int CB = (C4 + 255) / 256;

    copy_kernel<<<CB, 256>>>(core, raw, C4);
    if (out_mems) copy_kernel<<<CB, 256>>>(out_mems, raw, C4);
    pos_kernel<<<(KLEN * DIM + 255) / 256, 256>>>(pos);

    for (int i = 0; i < NLAY; i++) {
        copy_kernel<<<CB, 256>>>(cat, mems + (size_t)i * NE, C4);
        copy_kernel<<<CB, 256>>>(cat + NE, core, C4);

        // QKV split: mem rows need only K,V (cols 1024..3071); q rows need all.
        mma_gemm<<<dim3(16, 16), 256>>>(
            cat, qkvw + (size_t)i * DIM * 3 * DIM + 1024, wh + 1024,
            2048, 2048, 1024, 1024, 3072, 3072, nullptr, 0);
        mma_gemm<<<dim3(24, 16), 256>>>(
            cat + (size_t)2048 * 1024, qkvw + (size_t)i * DIM * 3 * DIM,
            wh + (size_t)2048 * 3072,
            2048, 3072, 1024, 1024, 3072, 3072, nullptr, 0);
        mma_gemm<<<dim3(8, 16), 256>>>(
            pos, rw + (size_t)i * DIM * DIM, rh,
            2048, 1024, 1024, 1024, 1024, 1024, nullptr, 0);

        attn_mma_kernel<<<dim3(16, 32), 256, ATTN2_SMEM_BYTES>>>(wh, rh, rwb, rrb, av);

        mma_gemm<<<dim3(8, 16), 256>>>(
            av, ow + (size_t)i * DIM * DIM, tmp,
            2048, 1024, 1024, 1024, 1024, 1024, nullptr, 0);
        ln_kernel<<<2048, 256>>>(tmp, core, ln1g + i * DIM, ln1b + i * DIM, core2, nullptr);

        mma_gemm<<<dim3(8, 16), 256>>>(
            core2, fw1 + (size_t)i * DIM * DIM, ff,
            2048, 1024, 1024, 1024, 1024, 1024, fb1 + i * DIM, 1);
        mma_gemm<<<dim3(8, 16), 256>>>(
            ff, fw2 + (size_t)i * DIM * DIM, tmp,
            2048, 1024, 1024, 1024, 1024, 1024, fb2 + i * DIM, 0);
        float* lnDst = (i == NLAY - 1) ? out : core;
        ln_kernel<<<2048, 256>>>(tmp, core2, ln2g + i * DIM, ln2b + i * DIM, lnDst,
                                 out_mems ? out_mems + (size_t)(i + 1) * NE : nullptr);
    }
}

// round 8
// speedup vs baseline: 5.2846x; 1.1052x over previous
#include <cuda_runtime.h>
#include <math.h>
#include <stdint.h>

#define L_Q   1024
#define BSZ   2
#define DIM   1024
#define NHEAD 16
#define DHEAD 64
#define NLAY  4
#define MLEN  1024
#define KLEN  2048
#define NE    (L_Q*BSZ*DIM)   /* 2097152 floats per (L,B,D) slab */

// ---------------- scratch (device globals; no allocation allowed) ----------------
__device__ float g_wheads[(size_t)KLEN*BSZ*3*DIM];   // 50 MB
__device__ float g_pos[(size_t)KLEN*DIM];            // 8 MB
__device__ float g_rhead[(size_t)KLEN*DIM];          // 8 MB
__device__ float g_attnvec[NE];
__device__ float g_tmp[NE];
__device__ float g_core[NE];
__device__ float g_core2[NE];
__device__ float g_ff[NE];

// ---------------- simple float4 copy ----------------
__global__ void copy_kernel(float* __restrict__ dst, const float* __restrict__ src, int n4) {
    int i = blockIdx.x * blockDim.x + threadIdx.x;
    if (i < n4) ((float4*)dst)[i] = ((const float4*)src)[i];
}

// ---------------- positional embedding ----------------
__global__ void pos_kernel(float* __restrict__ pos) {
    int idx = blockIdx.x * blockDim.x + threadIdx.x;
    if (idx >= KLEN * DIM) return;
    int j = idx >> 10;           // 0..2047
    int i = idx & 1023;          // 0..1023
    int t = i & 511;
    float x = (float)(2 * t) * (1.0f / 1024.0f);
    float invf = expf(-x * 9.210340371976184f);   // 10000^{-x}
    float arg = (float)(KLEN - 1 - j) * invf;
    pos[idx] = (i < 512) ? sinf(arg) : cosf(arg);
}

// ---------------- tf32 helpers ----------------
__device__ __forceinline__ uint32_t f2tf32(float f) {
    uint32_t u;
    asm("cvt.rna.tf32.f32 %0, %1;" : "=r"(u) : "f"(f));
    return u;
}
__device__ __forceinline__ uint4 cvt4(float4 v) {
    return make_uint4(f2tf32(v.x), f2tf32(v.y), f2tf32(v.z), f2tf32(v.w));
}
__device__ __forceinline__ void mma_tf32(float* c, const uint32_t* a, const uint32_t* b) {
    asm volatile(
        "mma.sync.aligned.m16n8k8.row.col.f32.tf32.tf32.f32 "
        "{%0,%1,%2,%3}, {%4,%5,%6,%7}, {%8,%9}, {%0,%1,%2,%3};"
        : "+f"(c[0]), "+f"(c[1]), "+f"(c[2]), "+f"(c[3])
        : "r"(a[0]), "r"(a[1]), "r"(a[2]), "r"(a[3]), "r"(b[0]), "r"(b[1]));
}

// ---------------- tf32 tensor-core GEMM: 128x128 block, K-tile 32, 2-stage ----
// A[M,K] lda, B[K,N] ldb, C[M,N] ldc (row-major). M,N %128==0, K%32==0.
__global__ __launch_bounds__(256) void mma_gemm(
    const float* __restrict__ A, const float* __restrict__ B, float* __restrict__ C,
    int M, int N, int K, int lda, int ldb, int ldc,
    const float* __restrict__ bias, int relu)
{
    __shared__ __align__(16) uint32_t As[2][4096];
    __shared__ __align__(16) uint32_t Bs[2][4096];

    const int tid = threadIdx.x;
    const int lane = tid & 31;
    const int w = tid >> 5;
    const int wr = w & 1;            // 0..1
    const int wc = w >> 1;           // 0..3
    const int bx = blockIdx.x, by = blockIdx.y;

    const int sar = tid >> 1;                 // A row 0..127
    const int sac = (tid & 1) << 4;           // A col base 0 or 16
    const int sbk = tid >> 3;                 // B k-row 0..31
    const int sbn = (tid & 7) << 4;           // B col base 0..112

    const float* Ag = A + (size_t)(by * 128 + sar) * lda + sac;
    const float* Bg = B + (size_t)sbk * ldb + bx * 128 + sbn;

    // precomputed staging destination offsets
    int aoff[4], boff[4];
    {
        const int mb = sar >> 4;
        const int lbase = (sar & 7) << 2;
        const int rq = (sar >> 3) & 1;
#pragma unroll
        for (int t = 0; t < 4; t++) {
            const int c = sac + t * 4;
            const int ks = c >> 3;
            const int q = rq + 2 * ((c >> 2) & 1);
            aoff[t] = (((ks * 8 + mb) * 32 + lbase) << 2) + q;
        }
        const int ksb = sbk >> 3;
        const int kq = (sbk >> 2) & 1;
        const int kt2 = (sbk & 3) << 1;
#pragma unroll
        for (int t = 0; t < 4; t++) {
            const int n = sbn + t * 4;
            const int nb = n >> 3;
            boff[t] = (((ksb * 16 + nb) * 32 + ((n & 7) << 2)) << 1) + kt2 + kq;
        }
    }

    float acc[4][4][4];
#pragma unroll
    for (int mi = 0; mi < 4; mi++)
#pragma unroll
        for (int ni = 0; ni < 4; ni++)
#pragma unroll
            for (int q = 0; q < 4; q++) acc[mi][ni][q] = 0.f;

    float4 pa[4], pb[4];
#pragma unroll
    for (int t = 0; t < 4; t++) {
        pa[t] = *(const float4*)(Ag + t * 4);
        pb[t] = *(const float4*)(Bg + t * 4);
    }
    // stage tile 0 -> buf 0
#pragma unroll
    for (int t = 0; t < 4; t++) {
        uint32_t* da = &As[0][aoff[t]];
        const float* fa = (const float*)&pa[t];
        da[0] = f2tf32(fa[0]); da[4] = f2tf32(fa[1]);
        da[8] = f2tf32(fa[2]); da[12] = f2tf32(fa[3]);
        uint32_t* db = &Bs[0][boff[t]];
        const float* fb = (const float*)&pb[t];
        db[0] = f2tf32(fb[0]); db[8] = f2tf32(fb[1]);
        db[16] = f2tf32(fb[2]); db[24] = f2tf32(fb[3]);
    }
    __syncthreads();

    const int NT = K >> 5;
    for (int T = 0; T < NT; T++) {
        const int buf = T & 1;
        if (T + 1 < NT) {
            const int off = (T + 1) << 5;
#pragma unroll
            for (int t = 0; t < 4; t++) {
                pa[t] = *(const float4*)(Ag + off + t * 4);
                pb[t] = *(const float4*)(Bg + (size_t)off * ldb + t * 4);
            }
        }
#pragma unroll
        for (int ks = 0; ks < 4; ks++) {
            uint32_t afr[4][4], bfr[4][2];
#pragma unroll
            for (int mi = 0; mi < 4; mi++) {
                const uint4 v = *(const uint4*)&As[buf][(((ks * 8 + wr * 4 + mi) * 32 + lane) << 2)];
                afr[mi][0] = v.x; afr[mi][1] = v.y; afr[mi][2] = v.z; afr[mi][3] = v.w;
            }
#pragma unroll
            for (int ni = 0; ni < 4; ni++) {
                const uint2 v = *(const uint2*)&Bs[buf][(((ks * 16 + wc * 4 + ni) * 32 + lane) << 1)];
                bfr[ni][0] = v.x; bfr[ni][1] = v.y;
            }
#pragma unroll
            for (int mi = 0; mi < 4; mi++)
#pragma unroll
                for (int ni = 0; ni < 4; ni++)
                    mma_tf32(acc[mi][ni], afr[mi], bfr[ni]);
        }
        if (T + 1 < NT) {
            const int nb2 = buf ^ 1;
#pragma unroll
            for (int t = 0; t < 4; t++) {
                uint32_t* da = &As[nb2][aoff[t]];
                const float* fa = (const float*)&pa[t];
                da[0] = f2tf32(fa[0]); da[4] = f2tf32(fa[1]);
                da[8] = f2tf32(fa[2]); da[12] = f2tf32(fa[3]);
                uint32_t* db = &Bs[nb2][boff[t]];
                const float* fb = (const float*)&pb[t];
                db[0] = f2tf32(fb[0]); db[8] = f2tf32(fb[1]);
                db[16] = f2tf32(fb[2]); db[24] = f2tf32(fb[3]);
            }
        }
        __syncthreads();
    }

    const int g = lane >> 2;
    const int t = lane & 3;
#pragma unroll
    for (int mi = 0; mi < 4; mi++) {
        const int r0 = by * 128 + wr * 64 + mi * 16 + g;
#pragma unroll
        for (int ni = 0; ni < 4; ni++) {
            const int c0 = bx * 128 + wc * 32 + ni * 8 + t * 2;
            float b0 = 0.f, b1 = 0.f;
            if (bias) { b0 = bias[c0]; b1 = bias[c0 + 1]; }
            float2 o0, o1;
            o0.x = acc[mi][ni][0] + b0; o0.y = acc[mi][ni][1] + b1;
            o1.x = acc[mi][ni][2] + b0; o1.y = acc[mi][ni][3] + b1;
            if (relu) {
                o0.x = fmaxf(o0.x, 0.f); o0.y = fmaxf(o0.y, 0.f);
                o1.x = fmaxf(o1.x, 0.f); o1.y = fmaxf(o1.y, 0.f);
            }
            *(float2*)&C[(size_t)r0 * ldc + c0] = o0;
            *(float2*)&C[(size_t)(r0 + 8) * ldc + c0] = o1;
        }
    }
}

// ---------------- tensor-core fused rel-attention (pitch-68 + E-band skip) ----
#define AT_QW 0                     /* 64x68 tf32 */
#define AT_QR 4352
#define AT_K  8704
#define AT_R  13056                 /* 128x68 (127 used) */
#define AT_V  21760
#define AT_S  26112                 /* 64x68 f32 */
#define AT_E  30464                 /* 64x136 f32 */
#define AT_P  39168                 /* 64x68 tf32 */
#define AT_M  43520
#define AT_L  43584
#define AT_A  43648
#define ATTN2_SMEM_FLOATS 43712
#define ATTN2_SMEM_BYTES  (ATTN2_SMEM_FLOATS * 4)

__global__ __launch_bounds__(256) void attn_mma_kernel(
    const float* __restrict__ wh, const float* __restrict__ rh,
    const float* __restrict__ rwb, const float* __restrict__ rrb,
    float* __restrict__ av)
{
    extern __shared__ float smf[];
    uint32_t* sQw = (uint32_t*)(smf + AT_QW);
    uint32_t* sQr = (uint32_t*)(smf + AT_QR);
    uint32_t* sK  = (uint32_t*)(smf + AT_K);
    uint32_t* sR  = (uint32_t*)(smf + AT_R);
    uint32_t* sV  = (uint32_t*)(smf + AT_V);
    float*    sS  = smf + AT_S;
    float*    sE  = smf + AT_E;
    uint32_t* sP  = (uint32_t*)(smf + AT_P);
    float*    sM  = smf + AT_M;
    float*    sL  = smf + AT_L;
    float*    sA  = smf + AT_A;

    const int i0 = (15 - blockIdx.x) << 6;   // heaviest q-tile first
    const int bi = blockIdx.y >> 4;
    const int hn = blockIdx.y & 15;
    const int tid = threadIdx.x;
    const int lane = tid & 31;
    const int w = tid >> 5;
    const int rb = w >> 1;           // 0..3
    const int ch = w & 1;            // 0..1
    const int g = lane >> 2;         // 0..7
    const int t = lane & 3;          // 0..3
    const int hbase = hn << 6;

    // E diagonal-band block bounds for this warp (rows 16rb..16rb+15, col half ch)
    int ebmin = 41 - 16 * rb - 64 * ch;
    ebmin = ebmin <= 0 ? 0 : ((ebmin + 7) >> 3);
    int ebmax = (126 - 16 * rb - 64 * ch) >> 3;
    if (ebmax > 7) ebmax = 7;

    // staging lane coords (float4 granularity)
    const int svr = tid >> 4;             // row 0..15 base (of 64, via +u*16)
    const int svc = (tid & 15) << 2;      // col 0,4,..,60

    // ---- load Q tiles (bias folded), vectorized ----
    {
        float4 w4 = *(const float4*)&rwb[hbase + svc];
        float4 r4 = *(const float4*)&rrb[hbase + svc];
#pragma unroll
        for (int u = 0; u < 4; u++) {
            const int r = svr + u * 16;
            const size_t base = ((size_t)((MLEN + i0 + r) * BSZ + bi)) * 3072 + hbase + svc;
            float4 q4 = *(const float4*)&wh[base];
            float4 aw = make_float4(q4.x + w4.x, q4.y + w4.y, q4.z + w4.z, q4.w + w4.w);
            float4 ar = make_float4(q4.x + r4.x, q4.y + r4.y, q4.z + r4.z, q4.w + r4.w);
            *(uint4*)&sQw[r * 68 + svc] = cvt4(aw);
            *(uint4*)&sQr[r * 68 + svc] = cvt4(ar);
        }
    }
    if (tid < 64) { sM[tid] = -3e38f; sL[tid] = 0.f; }

    float acc[4][4];   // PV accum frags
#pragma unroll
    for (int cb = 0; cb < 4; cb++)
#pragma unroll
        for (int q = 0; q < 4; q++) acc[cb][q] = 0.f;

    const int arow0 = (16 * rb + g) * 68;
    const int arow1 = (16 * rb + g + 8) * 68;
    const int nkt = 17 + (i0 >> 6);

    // K/V prefetch registers for tile 0
    float4 pk[4], pv[4];
#pragma unroll
    for (int u = 0; u < 4; u++) {
        const int r = svr + u * 16;
        const size_t base = ((size_t)(r * BSZ + bi)) * 3072 + hbase + svc;
        pk[u] = *(const float4*)&wh[base + 1024];
        pv[u] = *(const float4*)&wh[base + 2048];
    }

    for (int kt = 0; kt < nkt; kt++) {
        const int j0 = kt << 6;
        __syncthreads();
        // ---- store prefetched K/V; stage R directly ----
#pragma unroll
        for (int u = 0; u < 4; u++) {
            const int r = svr + u * 16;
            *(uint4*)&sK[r * 68 + svc] = cvt4(pk[u]);
            *(uint4*)&sV[r * 68 + svc] = cvt4(pv[u]);
        }
        const int rbase = j0 + MLEN - 1 - i0 - 63;
#pragma unroll
        for (int u = 0; u < 8; u++) {
            const int idx = tid + u * 256;
            if (idx < 2032) {
                const int r = idx >> 4, c4 = (idx & 15) << 2;
                int rg = rbase + r;
                rg = rg < 0 ? 0 : (rg > KLEN - 1 ? KLEN - 1 : rg);
                const float4 v = *(const float4*)&rh[(size_t)rg * DIM + hbase + c4];
                *(uint4*)&sR[r * 68 + c4] = cvt4(v);
            }
        }
        __syncthreads();

        // ---- prefetch next tile's K/V (overlaps mma below) ----
        if (kt + 1 < nkt) {
#pragma unroll
            for (int u = 0; u < 4; u++) {
                const int r = svr + u * 16;
                const size_t base = ((size_t)(((j0 + 64) + r) * BSZ + bi)) * 3072 + hbase + svc;
                pk[u] = *(const float4*)&wh[base + 1024];
                pv[u] = *(const float4*)&wh[base + 2048];
            }
        }

        // ---- S and E via mma (E restricted to diagonal band blocks) ----
        float Sacc[4][4], Eacc[8][4];
#pragma unroll
        for (int cb = 0; cb < 4; cb++)
#pragma unroll
            for (int q = 0; q < 4; q++) Sacc[cb][q] = 0.f;
#pragma unroll
        for (int eb = 0; eb < 8; eb++)
#pragma unroll
            for (int q = 0; q < 4; q++) Eacc[eb][q] = 0.f;

#pragma unroll
        for (int ks = 0; ks < 8; ks++) {
            const int kc = ks * 8 + t;
            uint32_t aw[4], ar[4];
            aw[0] = sQw[arow0 + kc]; aw[1] = sQw[arow1 + kc];
            aw[2] = sQw[arow0 + kc + 4]; aw[3] = sQw[arow1 + kc + 4];
            ar[0] = sQr[arow0 + kc]; ar[1] = sQr[arow1 + kc];
            ar[2] = sQr[arow0 + kc + 4]; ar[3] = sQr[arow1 + kc + 4];
#pragma unroll
            for (int cb = 0; cb < 4; cb++) {
                const int kr = (8 * (ch * 4 + cb) + g) * 68 + kc;
                uint32_t b[2] = { sK[kr], sK[kr + 4] };
                mma_tf32(Sacc[cb], aw, b);
            }
#pragma unroll
            for (int eb = 0; eb < 8; eb++) {
                if (eb >= ebmin && eb <= ebmax) {
                    const int rr = (8 * (ch * 8 + eb) + g) * 68 + kc;
                    uint32_t b[2] = { sR[rr], sR[rr + 4] };
                    mma_tf32(Eacc[eb], ar, b);
                }
            }
        }
        // write S, E to smem (float2 stores)
#pragma unroll
        for (int cb = 0; cb < 4; cb++) {
            const int col = 8 * (ch * 4 + cb) + 2 * t;
            *(float2*)&sS[(16 * rb + g) * 68 + col]     = make_float2(Sacc[cb][0], Sacc[cb][1]);
            *(float2*)&sS[(16 * rb + g + 8) * 68 + col] = make_float2(Sacc[cb][2], Sacc[cb][3]);
        }
#pragma unroll
        for (int eb = 0; eb < 8; eb++) {
            if (eb >= ebmin && eb <= ebmax) {
                const int col = 8 * (ch * 8 + eb) + 2 * t;
                *(float2*)&sE[(16 * rb + g) * 136 + col]     = make_float2(Eacc[eb][0], Eacc[eb][1]);
                *(float2*)&sE[(16 * rb + g + 8) * 136 + col] = make_float2(Eacc[eb][2], Eacc[eb][3]);
            }
        }
        __syncthreads();

        // ---- online softmax: warp w owns rows w*8..w*8+7; lane quad per row ----
        {
            const int row = w * 8 + g;
            const int qi = i0 + row;
            float sarr[16];
            {
                const float4* srow = (const float4*)&sS[row * 68 + t * 16];
#pragma unroll
                for (int v4 = 0; v4 < 4; v4++) {
                    float4 s4 = srow[v4];
                    sarr[v4 * 4 + 0] = s4.x; sarr[v4 * 4 + 1] = s4.y;
                    sarr[v4 * 4 + 2] = s4.z; sarr[v4 * 4 + 3] = s4.w;
                }
            }
            const int ebase = row * 135 + t * 16 + 63;   // row*136 + (t*16 - row + 63)
            float tmax = -3e38f;
#pragma unroll
            for (int e = 0; e < 16; e++) {
                float vv = (sarr[e] + sE[ebase + e]) * 0.125f;
                if (j0 + t * 16 + e > MLEN + qi) vv = -3e38f;
                sarr[e] = vv;
                tmax = fmaxf(tmax, vv);
            }
            tmax = fmaxf(tmax, __shfl_xor_sync(0xffffffffu, tmax, 1));
            tmax = fmaxf(tmax, __shfl_xor_sync(0xffffffffu, tmax, 2));
            const float mold = sM[row];
            const float mnew = fmaxf(mold, tmax);
            float rsum = 0.f;
            uint32_t pb[16];
#pragma unroll
            for (int e = 0; e < 16; e++) {
                float p = __expf(sarr[e] - mnew);
                rsum += p;
                pb[e] = f2tf32(p);
            }
            rsum += __shfl_xor_sync(0xffffffffu, rsum, 1);
            rsum += __shfl_xor_sync(0xffffffffu, rsum, 2);
            if (t == 0) {
                const float al = __expf(mold - mnew);
                sM[row] = mnew;
                sA[row] = al;
                sL[row] = sL[row] * al + rsum;
            }
            uint4* pd = (uint4*)&sP[row * 68 + t * 16];
            pd[0] = make_uint4(pb[0], pb[1], pb[2], pb[3]);
            pd[1] = make_uint4(pb[4], pb[5], pb[6], pb[7]);
            pd[2] = make_uint4(pb[8], pb[9], pb[10], pb[11]);
            pd[3] = make_uint4(pb[12], pb[13], pb[14], pb[15]);
        }
        __syncthreads();

        // ---- rescale + P@V via mma ----
        {
            const float al0 = sA[16 * rb + g];
            const float al1 = sA[16 * rb + g + 8];
#pragma unroll
            for (int cb = 0; cb < 4; cb++) {
                acc[cb][0] *= al0; acc[cb][1] *= al0;
                acc[cb][2] *= al1; acc[cb][3] *= al1;
            }
            const int prow0 = (16 * rb + g) * 68;
            const int prow1 = (16 * rb + g + 8) * 68;
#pragma unroll
            for (int ks = 0; ks < 8; ks++) {
                const int kc = ks * 8 + t;
                uint32_t a[4] = { sP[prow0 + kc], sP[prow1 + kc],
                                  sP[prow0 + kc + 4], sP[prow1 + kc + 4] };
#pragma unroll
                for (int cb = 0; cb < 4; cb++) {
                    const int col = 8 * (ch * 4 + cb) + g;
                    uint32_t b[2] = { sV[(ks * 8 + t) * 68 + col],
                                      sV[(ks * 8 + t + 4) * 68 + col] };
                    mma_tf32(acc[cb], a, b);
                }
            }
        }
    }

    // ---- finalize ----
    const float linv0 = 1.f / sL[16 * rb + g];
    const float linv1 = 1.f / sL[16 * rb + g + 8];
    const int r0 = i0 + 16 * rb + g;
#pragma unroll
    for (int cb = 0; cb < 4; cb++) {
        const int col = hbase + 8 * (ch * 4 + cb) + 2 * t;
        float2 o0, o1;
        o0.x = acc[cb][0] * linv0; o0.y = acc[cb][1] * linv0;
        o1.x = acc[cb][2] * linv1; o1.y = acc[cb][3] * linv1;
        *(float2*)&av[((size_t)(r0 * BSZ + bi)) * DIM + col] = o0;
        *(float2*)&av[((size_t)((r0 + 8) * BSZ + bi)) * DIM + col] = o1;
    }
}

// ---------------- residual + layernorm (row per block) ----------------
__global__ __launch_bounds__(256) void ln_kernel(
    const float* __restrict__ x, const float* __restrict__ res,
    const float* __restrict__ g, const float* __restrict__ b,
    float* __restrict__ out1, float* __restrict__ out2)
{
    const int row = blockIdx.x;
    const int tid = threadIdx.x;
    float4 xv = *(const float4*)(x + (size_t)row * DIM + tid * 4);
    float4 rv = *(const float4*)(res + (size_t)row * DIM + tid * 4);
    float v0 = xv.x + rv.x, v1 = xv.y + rv.y, v2 = xv.z + rv.z, v3 = xv.w + rv.w;
    float s = v0 + v1 + v2 + v3;
    float q = v0 * v0 + v1 * v1 + v2 * v2 + v3 * v3;
#pragma unroll
    for (int off = 16; off > 0; off >>= 1) {
        s += __shfl_xor_sync(0xffffffffu, s, off);
        q += __shfl_xor_sync(0xffffffffu, q, off);
    }
    __shared__ float sb[8], qb[8];
    const int w = tid >> 5, lane = tid & 31;
    if (lane == 0) { sb[w] = s; qb[w] = q; }
    __syncthreads();
    if (w == 0) {
        float s2 = (lane < 8) ? sb[lane] : 0.f;
        float q2 = (lane < 8) ? qb[lane] : 0.f;
#pragma unroll
        for (int off = 4; off > 0; off >>= 1) {
            s2 += __shfl_xor_sync(0xffffffffu, s2, off);
            q2 += __shfl_xor_sync(0xffffffffu, q2, off);
        }
        if (lane == 0) { sb[0] = s2; qb[0] = q2; }
    }
    __syncthreads();
    const float mean = sb[0] * (1.0f / DIM);
    const float var  = qb[0] * (1.0f / DIM) - mean * mean;
    const float rstd = rsqrtf(var + 1e-5f);
    float4 gv = *(const float4*)(g + tid * 4);
    float4 bv = *(const float4*)(b + tid * 4);
    float4 o;
    o.x = (v0 - mean) * rstd * gv.x + bv.x;
    o.y = (v1 - mean) * rstd * gv.y + bv.y;
    o.z = (v2 - mean) * rstd * gv.z + bv.z;
    o.w = (v3 - mean) * rstd * gv.w + bv.w;
    *(float4*)(out1 + (size_t)row * DIM + tid * 4) = o;
    if (out2) *(float4*)(out2 + (size_t)row * DIM + tid * 4) = o;
}

// ---------------- host orchestration ----------------
extern "C" void kernel_launch(void* const* d_in, const int* in_sizes, int n_in,
                              void* d_out, int out_size) {
    const float* mems = (const float*)d_in[0];
    const float* raw  = (const float*)d_in[1];
    /* d_in[2] = attention_mask: analytic, ignored */
    const float* rwb  = (const float*)d_in[3];
    const float* rrb  = (const float*)d_in[4];
    const float* qkvw = (const float*)d_in[5];
    const float* rw   = (const float*)d_in[6];
    const float* ow   = (const float*)d_in[7];
    const float* ln1g = (const float*)d_in[8];
    const float* ln1b = (const float*)d_in[9];
    const float* fw1  = (const float*)d_in[10];
    const float* fb1  = (const float*)d_in[11];
    const float* fw2  = (const float*)d_in[12];
    const float* fb2  = (const float*)d_in[13];
    const float* ln2g = (const float*)d_in[14];
    const float* ln2b = (const float*)d_in[15];
    float* out = (float*)d_out;

    const bool full_out = out_size >= (NLAY + 2) * NE;   // core + new_mems(5 slabs)
    float* out_mems = full_out ? out + NE : nullptr;

    float *wh, *pos, *rh, *av, *tmp, *core, *core2, *ff;
    cudaGetSymbolAddress((void**)&wh,   g_wheads);
    cudaGetSymbolAddress((void**)&pos,  g_pos);
    cudaGetSymbolAddress((void**)&rh,   g_rhead);
    cudaGetSymbolAddress((void**)&av,   g_attnvec);
    cudaGetSymbolAddress((void**)&tmp,  g_tmp);
    cudaGetSymbolAddress((void**)&core, g_core);
    cudaGetSymbolAddress((void**)&core2,g_core2);
    cudaGetSymbolAddress((void**)&ff,   g_ff);

    cudaFuncSetAttribute((const void*)attn_mma_kernel,
                         cudaFuncAttributeMaxDynamicSharedMemorySize, ATTN2_SMEM_BYTES);

    const int C4 = NE / 4;               // float4 count per slab
    const int CB = (C4 + 255) / 256;

    copy_kernel<<<CB, 256>>>(core, raw, C4);
    if (out_mems) copy_kernel<<<CB, 256>>>(out_mems, raw, C4);
    pos_kernel<<<(KLEN * DIM + 255) / 256, 256>>>(pos);

    for (int i = 0; i < NLAY; i++) {
        // QKV split, reading sources directly (no cat buffer):
        //  - mem rows (from mems[i]) need only K,V (cols 1024..3071)
        //  - q rows (from core) need all 3072 cols
        mma_gemm<<<dim3(16, 16), 256>>>(
            mems + (size_t)i * NE, qkvw + (size_t)i * DIM * 3 * DIM + 1024, wh + 1024,
            2048, 2048, 1024, 1024, 3072, 3072, nullptr, 0);
        mma_gemm<<<dim3(24, 16), 256>>>(
            core, qkvw + (size_t)i * DIM * 3 * DIM,
            wh + (size_t)2048 * 3072,
            2048, 3072, 1024, 1024, 3072, 3072, nullptr, 0);
        mma_gemm<<<dim3(8, 16), 256>>>(
            pos, rw + (size_t)i * DIM * DIM, rh,
            2048, 1024, 1024, 1024, 1024, 1024, nullptr, 0);

        attn_mma_kernel<<<dim3(16, 32), 256, ATTN2_SMEM_BYTES>>>(wh, rh, rwb, rrb, av);

        mma_gemm<<<dim3(8, 16), 256>>>(
            av, ow + (size_t)i * DIM * DIM, tmp,
            2048, 1024, 1024, 1024, 1024, 1024, nullptr, 0);
        ln_kernel<<<2048, 256>>>(tmp, core, ln1g + i * DIM, ln1b + i * DIM, core2, nullptr);

        mma_gemm<<<dim3(8, 16), 256>>>(
            core2, fw1 + (size_t)i * DIM * DIM, ff,
            2048, 1024, 1024, 1024, 1024, 1024, fb1 + i * DIM, 1);
        mma_gemm<<<dim3(8, 16), 256>>>(
            ff, fw2 + (size_t)i * DIM * DIM, tmp,
            2048, 1024, 1024, 1024, 1024, 1024, fb2 + i * DIM, 0);
        float* lnDst = (i == NLAY - 1) ? out : core;
        ln_kernel<<<2048, 256>>>(tmp, core2, ln2g + i * DIM, ln2b + i * DIM, lnDst,
                                 out_mems ? out_mems + (size_t)(i + 1) * NE : nullptr);
    }
}